// round 13
// baseline (speedup 1.0000x reference)
#include <cuda_runtime.h>
#include <cuda_bf16.h>
#include <cstdint>

#define T_LEN 2048
#define C_DIM 2048
#define H_NUM 16
#define N_DIM 128
#define KVH_NUM 4
#define HN_DIM 2048
#define KVN_DIM 512

// fused stage-1 output column offsets
#define OFF_XR 0
#define OFF_XK 2048
#define OFF_XV 2560
#define OFF_TW 3072
#define OFF_TA 3232
#define OFF_TV 3328
#define OFF_TK 3392
#define OFF_TG 3456
#define NCAT 3616
#define NMID 544

// stage-2 A' regions inside g_Ap (element offsets; row stride = 2*K)
#define APW_BASE 0         // K=160 -> stride 320
#define APA_BASE 655360    // K=96  -> stride 192
#define APG_BASE 1048576   // K=160 -> stride 320
#define APV_BASE 1703936   // K=64  -> stride 128
#define APK_BASE 1966080   // K=64  -> stride 128

// stage-2 B' regions inside g_Bp (element offsets; 2K rows x N)
#define BW_BASE 0
#define BA_BASE 655360
#define BG_BASE 1048576
#define BV_BASE 1703936
#define BK_BASE 1769472

// ---------------- scratch ----------------
__device__ float g_Ccat[(size_t)T_LEN * NCAT];
__device__ float g_wfull[T_LEN * HN_DIM];
__device__ float g_afull[T_LEN * HN_DIM];
__device__ float g_gfull[T_LEN * HN_DIM];
__device__ float g_vmix[T_LEN * KVN_DIM];
__device__ float g_kmix[T_LEN * KVN_DIM];
__device__ float g_rr[T_LEN * HN_DIM];
__device__ float g_kf[T_LEN * KVN_DIM];
__device__ float g_vf[T_LEN * KVN_DIM];
__device__ float g_kk[T_LEN * KVN_DIM];
__device__ float g_wd[T_LEN * HN_DIM];
__device__ float g_bb[T_LEN * HN_DIM];
__device__ float g_coef[T_LEN * H_NUM];
__device__ float2 g_c12[T_LEN * H_NUM];
__device__ float g_y[T_LEN * HN_DIM];

__device__ __nv_bfloat16 g_Ap[(size_t)2048 * 2 * 2048];   // [hi | lo], M x 2K
__device__ __nv_bfloat16 g_Bp[(size_t)2 * 2048 * NCAT];   // [hi ; lo], 2K x ldB

// ---------------- helpers ----------------
__device__ __forceinline__ float sigmoidf_(float x) { return 1.0f / (1.0f + expf(-x)); }

__device__ __forceinline__ float blockReduceSum128(float v, float* red) {
#pragma unroll
    for (int m = 16; m > 0; m >>= 1) v += __shfl_xor_sync(0xffffffffu, v, m);
    __syncthreads();
    if ((threadIdx.x & 31) == 0) red[threadIdx.x >> 5] = v;
    __syncthreads();
    return red[0] + red[1] + red[2] + red[3];
}

__device__ __forceinline__ void blockReduceSum3(float& a, float& b, float& c,
                                                float (*red)[3]) {
#pragma unroll
    for (int m = 16; m > 0; m >>= 1) {
        a += __shfl_xor_sync(0xffffffffu, a, m);
        b += __shfl_xor_sync(0xffffffffu, b, m);
        c += __shfl_xor_sync(0xffffffffu, c, m);
    }
    __syncthreads();
    if ((threadIdx.x & 31) == 0) {
        int w = threadIdx.x >> 5;
        red[w][0] = a;
        red[w][1] = b;
        red[w][2] = c;
    }
    __syncthreads();
    a = red[0][0] + red[1][0] + red[2][0] + red[3][0];
    b = red[0][1] + red[1][1] + red[2][1] + red[3][1];
    c = red[0][2] + red[1][2] + red[2][2] + red[3][2];
}

// packed f32x2 ops (sm_103a)
typedef unsigned long long ull;
__device__ __forceinline__ ull pack2(float x, float y) {
    ull r;
    asm("mov.b64 %0, {%1, %2};" : "=l"(r) : "f"(x), "f"(y));
    return r;
}
__device__ __forceinline__ float2 unpack2(ull v) {
    float x, y;
    asm("mov.b64 {%0, %1}, %2;" : "=f"(x), "=f"(y) : "l"(v));
    return make_float2(x, y);
}
__device__ __forceinline__ ull fma2_(ull a, ull b, ull c) {
    ull d;
    asm("fma.rn.f32x2 %0, %1, %2, %3;" : "=l"(d) : "l"(a), "l"(b), "l"(c));
    return d;
}
__device__ __forceinline__ ull mul2_(ull a, ull b) {
    ull d;
    asm("mul.rn.f32x2 %0, %1, %2;" : "=l"(d) : "l"(a), "l"(b));
    return d;
}

__device__ __forceinline__ uint32_t packsplit_hi(float a, float b) {
    __nv_bfloat162 h = __floats2bfloat162_rn(a, b);
    return *(uint32_t*)&h;
}
__device__ __forceinline__ uint32_t packsplit_lo(float a, float b, uint32_t hipack) {
    __nv_bfloat162* hp = (__nv_bfloat162*)&hipack;
    float ra = a - __bfloat162float(hp->x);
    float rb = b - __bfloat162float(hp->y);
    __nv_bfloat162 l = __floats2bfloat162_rn(ra, rb);
    return *(uint32_t*)&l;
}

// ---------------- split conversions (dedup: store hi+lo ONCE) ----------------
__global__ void splitAmask_kernel(const float* __restrict__ x, const float* __restrict__ mask,
                                  __nv_bfloat16* __restrict__ Ap, int n2) {
    int i = blockIdx.x * blockDim.x + threadIdx.x;
    if (i >= n2) return;
    int i2 = i * 2;
    int r = i2 >> 11, c = i2 & 2047;
    float2 xv = *(const float2*)&x[i2];
    float m = mask[r];
    float v0 = xv.x * m, v1 = xv.y * m;
    uint32_t hi = packsplit_hi(v0, v1);
    uint32_t lo = packsplit_lo(v0, v1, hi);
    size_t base = (size_t)r * 4096 + c;
    *(uint32_t*)&Ap[base] = hi;
    *(uint32_t*)&Ap[base + 2048] = lo;
}

__global__ void splitBcat_kernel(const float* __restrict__ W_r, const float* __restrict__ W_k,
                                 const float* __restrict__ W_v, const float* __restrict__ w1,
                                 const float* __restrict__ a1, const float* __restrict__ v1,
                                 const float* __restrict__ k1, const float* __restrict__ g1,
                                 __nv_bfloat16* __restrict__ Bp, int n2) {
    int i = blockIdx.x * blockDim.x + threadIdx.x;
    if (i >= n2) return;
    int i2 = i * 2;
    int r = i2 / NCAT, c = i2 - r * NCAT;
    const float* src;
    int off, ncols;
    if (c < 2048) { src = W_r; off = OFF_XR; ncols = 2048; }
    else if (c < 2560) { src = W_k; off = OFF_XK; ncols = 512; }
    else if (c < 3072) { src = W_v; off = OFF_XV; ncols = 512; }
    else if (c < 3232) { src = w1; off = OFF_TW; ncols = 160; }
    else if (c < 3328) { src = a1; off = OFF_TA; ncols = 96; }
    else if (c < 3392) { src = v1; off = OFF_TV; ncols = 64; }
    else if (c < 3456) { src = k1; off = OFF_TK; ncols = 64; }
    else { src = g1; off = OFF_TG; ncols = 160; }
    float2 xv = *(const float2*)&src[(size_t)r * ncols + (c - off)];
    uint32_t hi = packsplit_hi(xv.x, xv.y);
    uint32_t lo = packsplit_lo(xv.x, xv.y, hi);
    size_t base = (size_t)r * NCAT + c;
    *(uint32_t*)&Bp[base] = hi;
    *(uint32_t*)&Bp[base + (size_t)2048 * NCAT] = lo;
}

__global__ void splitB_kernel(const float* __restrict__ B, __nv_bfloat16* __restrict__ Bp,
                              int K, int Ncols, int ldB, int colOff, int n2) {
    int i = blockIdx.x * blockDim.x + threadIdx.x;
    if (i >= n2) return;
    int i2 = i * 2;
    int r = i2 / Ncols, c = i2 - r * Ncols;
    float2 xv = *(const float2*)&B[i2];
    uint32_t hi = packsplit_hi(xv.x, xv.y);
    uint32_t lo = packsplit_lo(xv.x, xv.y, hi);
    size_t base = (size_t)r * ldB + colOff + c;
    *(uint32_t*)&Bp[base] = hi;
    *(uint32_t*)&Bp[base + (size_t)K * ldB] = lo;
}

__global__ void splitB2_kernel(const float* __restrict__ w2, const float* __restrict__ a2,
                               const float* __restrict__ g2, const float* __restrict__ v2,
                               const float* __restrict__ k2, __nv_bfloat16* __restrict__ Bp,
                               int n2) {
    int i = blockIdx.x * blockDim.x + threadIdx.x;
    if (i >= n2) return;
    int i2 = i * 2;
    const float* src;
    int K, N, local;
    size_t base;
    if (i2 < 327680) { src = w2; K = 160; N = 2048; base = BW_BASE; local = i2; }
    else if (i2 < 524288) { src = a2; K = 96; N = 2048; base = BA_BASE; local = i2 - 327680; }
    else if (i2 < 851968) { src = g2; K = 160; N = 2048; base = BG_BASE; local = i2 - 524288; }
    else if (i2 < 884736) { src = v2; K = 64; N = 512; base = BV_BASE; local = i2 - 851968; }
    else { src = k2; K = 64; N = 512; base = BK_BASE; local = i2 - 884736; }
    float2 xv = *(const float2*)&src[local];
    uint32_t hi = packsplit_hi(xv.x, xv.y);
    uint32_t lo = packsplit_lo(xv.x, xv.y, hi);
    size_t off = base + (size_t)local;
    *(uint32_t*)&Bp[off] = hi;
    *(uint32_t*)&Bp[off + (size_t)K * N] = lo;
}

// ---------------- fused act + stage-2 A-split from Ccat: [hi | lo], stride 2K ----------------
__global__ void splitMids_kernel(const float* __restrict__ Ccat, __nv_bfloat16* __restrict__ Ap,
                                 int n2) {
    int i = blockIdx.x * blockDim.x + threadIdx.x;
    if (i >= n2) return;
    int i2 = i * 2;
    int t = i2 / NMID, c = i2 - t * NMID;
    const float* src = &Ccat[(size_t)t * NCAT + OFF_TW];
    float v0 = src[c], v1 = src[c + 1];
    int K, lc;
    size_t base;
    if (c < 160) {
        v0 = tanhf(v0); v1 = tanhf(v1);
        K = 160; base = APW_BASE; lc = c;
    } else if (c < 256) {
        K = 96; base = APA_BASE; lc = c - 160;
    } else if (c < 320) {
        K = 64; base = APV_BASE; lc = c - 256;
    } else if (c < 384) {
        K = 64; base = APK_BASE; lc = c - 320;
    } else {
        v0 = sigmoidf_(v0); v1 = sigmoidf_(v1);
        K = 160; base = APG_BASE; lc = c - 384;
    }
    uint32_t hi = packsplit_hi(v0, v1);
    uint32_t lo = packsplit_lo(v0, v1, hi);
    size_t off = base + (size_t)t * (2 * K) + lc;
    *(uint32_t*)&Ap[off] = hi;
    *(uint32_t*)&Ap[off + K] = lo;
}

// ---------------- fused merge + final A-split: [hi | lo], stride 4096 ----------------
__global__ void mergeSplitA_kernel(const float* __restrict__ y, const float* __restrict__ coef,
                                   const float* __restrict__ vf, const float* __restrict__ gbuf,
                                   __nv_bfloat16* __restrict__ Ap, int n2) {
    int i = blockIdx.x * blockDim.x + threadIdx.x;
    if (i >= n2) return;
    int i2 = i * 2;
    int t = i2 >> 11, hn = i2 & 2047;
    int h = hn >> 7, nn = hn & 127;
    float cf = coef[t * H_NUM + h];
    const float* vp = &vf[t * KVN_DIM + (h >> 2) * 128 + nn];
    float2 yv = *(const float2*)&y[i2];
    float2 gv = *(const float2*)&gbuf[i2];
    float v0 = (yv.x + cf * vp[0]) * gv.x;
    float v1 = (yv.y + cf * vp[1]) * gv.y;
    uint32_t hi = packsplit_hi(v0, v1);
    uint32_t lo = packsplit_lo(v0, v1, hi);
    size_t base = (size_t)t * 4096 + hn;
    *(uint32_t*)&Ap[base] = hi;
    *(uint32_t*)&Ap[base + 2048] = lo;
}

// ---------------- bf16 tensor-core GEMM with hi/lo-fused K-chunks ----------------
// A [M, 2*Kb] = [hi | lo] row-major; B [2*Kb, ldB] = [hi ; lo].
// Per 32-phys-K iteration: load A hi+lo (128x64) and B hi+lo (64x128) once,
// run 3 compute passes: hi*hi + lo*hi + hi*lo. Same products as K-tripled GEMM,
// 33% less L2 traffic and 3x fewer barrier iterations.
#define LDA_S 72
#define LDB_S 136
#define NSTAGE 2

__global__ __launch_bounds__(256) void bf16_gemm_kernel(
    const __nv_bfloat16* __restrict__ A, const __nv_bfloat16* __restrict__ B,
    float* __restrict__ C, int M, int N, int Kb, int ldB, int ldC) {
    __shared__ __align__(16) __nv_bfloat16 As[NSTAGE][128 * LDA_S];  // 128 rows x (32 hi | 32 lo)
    __shared__ __align__(16) __nv_bfloat16 Bs[NSTAGE][64 * LDB_S];   // (32 hi ; 32 lo) x 128

    const int tid = threadIdx.x;
    const int bm = blockIdx.y * 128;
    const int bn = blockIdx.x * 128;
    const int warp = tid >> 5;
    const int lane = tid & 31;
    const int wm = warp & 3;
    const int wn = warp >> 2;
    const int lda = 2 * Kb;

    // A loads: 128 rows x 64 cols, 4x16B per thread
    const int ar = tid >> 1;
    // B loads: 64 rows x 128 cols, 4x16B per thread
    const int br = tid >> 2;

    float c[2][8][4];
#pragma unroll
    for (int mi = 0; mi < 2; mi++)
#pragma unroll
        for (int ni = 0; ni < 8; ni++)
#pragma unroll
            for (int q = 0; q < 4; q++) c[mi][ni][q] = 0.0f;

    const int KT = Kb >> 5;

    auto load_stage = [&](int st, int kt) {
        int k0 = kt * 32;
        const __nv_bfloat16* aRow = A + (size_t)(bm + ar) * lda;
#pragma unroll
        for (int i = 0; i < 4; i++) {
            int cc = (tid & 1) * 32 + i * 8;                    // 0..63
            int pc = (cc < 32) ? (k0 + cc) : (Kb + k0 + cc - 32);
            uint32_t dst = (uint32_t)__cvta_generic_to_shared(&As[st][ar * LDA_S + cc]);
            asm volatile("cp.async.ca.shared.global [%0], [%1], 16;\n" ::"r"(dst),
                         "l"(aRow + pc));
        }
        int pr = (br < 32) ? (k0 + br) : (Kb + k0 + br - 32);
        const __nv_bfloat16* bRow = B + (size_t)pr * ldB + bn;
#pragma unroll
        for (int i = 0; i < 4; i++) {
            int c8 = (tid & 3) * 8 + i * 32;                    // 0..127
            int sz = ((bn + c8) < N) ? 16 : 0;
            uint32_t dst = (uint32_t)__cvta_generic_to_shared(&Bs[st][br * LDB_S + c8]);
            asm volatile("cp.async.ca.shared.global [%0], [%1], 16, %2;\n" ::"r"(dst),
                         "l"(bRow + c8), "r"(sz));
        }
        asm volatile("cp.async.commit_group;\n");
    };

    auto compute_stage = [&](int st, int aoff, int boff) {
#pragma unroll
        for (int kk = 0; kk < 32; kk += 16) {
            uint32_t af[2][4];
#pragma unroll
            for (int mi = 0; mi < 2; mi++) {
                uint32_t addr = (uint32_t)__cvta_generic_to_shared(
                    &As[st][(wm * 32 + mi * 16 + (lane & 15)) * LDA_S + aoff + kk +
                            (lane >> 4) * 8]);
                asm volatile("ldmatrix.sync.aligned.m8n8.x4.shared.b16 {%0,%1,%2,%3}, [%4];\n"
                             : "=r"(af[mi][0]), "=r"(af[mi][1]), "=r"(af[mi][2]), "=r"(af[mi][3])
                             : "r"(addr));
            }
            uint32_t bfr[8][2];
#pragma unroll
            for (int p = 0; p < 4; p++) {
                uint32_t addr = (uint32_t)__cvta_generic_to_shared(
                    &Bs[st][(boff + kk + (lane & 15)) * LDB_S + wn * 64 + p * 16 +
                            (lane >> 4) * 8]);
                uint32_t b0, b1, b2, b3;
                asm volatile("ldmatrix.sync.aligned.m8n8.x4.trans.shared.b16 {%0,%1,%2,%3}, [%4];\n"
                             : "=r"(b0), "=r"(b1), "=r"(b2), "=r"(b3)
                             : "r"(addr));
                bfr[p * 2][0] = b0;
                bfr[p * 2][1] = b1;
                bfr[p * 2 + 1][0] = b2;
                bfr[p * 2 + 1][1] = b3;
            }
#pragma unroll
            for (int mi = 0; mi < 2; mi++)
#pragma unroll
                for (int ni = 0; ni < 8; ni++) {
                    asm volatile(
                        "mma.sync.aligned.m16n8k16.row.col.f32.bf16.bf16.f32 "
                        "{%0,%1,%2,%3}, {%4,%5,%6,%7}, {%8,%9}, {%0,%1,%2,%3};\n"
                        : "+f"(c[mi][ni][0]), "+f"(c[mi][ni][1]), "+f"(c[mi][ni][2]),
                          "+f"(c[mi][ni][3])
                        : "r"(af[mi][0]), "r"(af[mi][1]), "r"(af[mi][2]), "r"(af[mi][3]),
                          "r"(bfr[ni][0]), "r"(bfr[ni][1]));
                }
        }
    };

    load_stage(0, 0);
    for (int kt = 0; kt < KT; kt++) {
        int st = kt & 1;
        if (kt + 1 < KT) {
            load_stage(st ^ 1, kt + 1);
            asm volatile("cp.async.wait_group 1;\n");
        } else {
            asm volatile("cp.async.wait_group 0;\n");
        }
        __syncthreads();
        compute_stage(st, 0, 0);    // hi * hi
        compute_stage(st, 32, 0);   // lo * hi
        compute_stage(st, 0, 32);   // hi * lo
        __syncthreads();
    }

#pragma unroll
    for (int mi = 0; mi < 2; mi++) {
        int row = bm + wm * 32 + mi * 16 + (lane >> 2);
#pragma unroll
        for (int ni = 0; ni < 8; ni++) {
            int col = bn + wn * 64 + ni * 8 + (lane & 3) * 2;
            if (col < N) {
                C[(size_t)row * ldC + col] = c[mi][ni][0];
                C[(size_t)row * ldC + col + 1] = c[mi][ni][1];
                C[(size_t)(row + 8) * ldC + col] = c[mi][ni][2];
                C[(size_t)(row + 8) * ldC + col + 1] = c[mi][ni][3];
            }
        }
    }
}

// ---------------- postprocess per (t, kvh) ----------------
__global__ void pp_kv_kernel(const float* __restrict__ Ccat,
                             const float* __restrict__ kmix, const float* __restrict__ vmix,
                             const float* __restrict__ k_first, const float* __restrict__ v_first,
                             const float* __restrict__ k0, const float* __restrict__ v0,
                             const float* __restrict__ knw, const float* __restrict__ cosb,
                             const float* __restrict__ sinb,
                             float* __restrict__ kf, float* __restrict__ vfout,
                             float* __restrict__ kkout) {
    int t = blockIdx.x, kvh = blockIdx.y, n = threadIdx.x;
    int idx = t * KVN_DIM + kvh * 128 + n;
    size_t cidx = (size_t)t * NCAT + kvh * 128 + n;
    __shared__ float shk[128];
    __shared__ float red[4];

    float k = Ccat[cidx + OFF_XK];
    float ss = blockReduceSum128(k * k, red);
    float kn = knw[n] * k * rsqrtf(ss * (1.0f / 128.0f) + 1e-6f);
    shk[n] = kn;
    __syncthreads();
    float rh = (n < 64) ? -shk[n + 64] : shk[n - 64];
    float c = cosb[t * 128 + n], s = sinb[t * 128 + n];
    float kr = fmaf(kn, c, rh * s);

    float kfv = kr + (k_first[idx] - kr) * sigmoidf_(k0[kvh * 128 + n] + kmix[idx]);
    float vv = Ccat[cidx + OFF_XV];
    float vfv = vv + (v_first[idx] - vv) * sigmoidf_(v0[kvh * 128 + n] + vmix[idx]);

    float nrm2 = blockReduceSum128(kfv * kfv, red);
    float denom = fmaxf(sqrtf(nrm2), 1e-12f);

    kf[idx] = kfv;
    vfout[idx] = vfv;
    kkout[idx] = kfv / denom;
}

// ---------------- postprocess per (t, h) ----------------
__global__ void pp_h_kernel(const float* __restrict__ Ccat, const float* __restrict__ wfull,
                            const float* __restrict__ afull,
                            const float* __restrict__ w0, const float* __restrict__ a0,
                            const float* __restrict__ kkbuf, const float* __restrict__ kfbuf,
                            const float* __restrict__ rnw, const float* __restrict__ cosb,
                            const float* __restrict__ sinb, const float* __restrict__ r_k,
                            float* __restrict__ rout, float* __restrict__ wdout,
                            float* __restrict__ bbout, float* __restrict__ coef,
                            float2* __restrict__ c12) {
    int t = blockIdx.x, h = blockIdx.y, n = threadIdx.x;
    int hn = h * 128 + n;
    int idx = t * HN_DIM + hn;
    __shared__ float shr[128];
    __shared__ float red[4];
    __shared__ float red3[4][3];

    float r = Ccat[(size_t)t * NCAT + OFF_XR + hn];
    float ss = blockReduceSum128(r * r, red);
    float rn = rnw[n] * r * rsqrtf(ss * (1.0f / 128.0f) + 1e-6f);
    shr[n] = rn;
    __syncthreads();
    float rh = (n < 64) ? -shr[n + 64] : shr[n - 64];
    float c = cosb[t * 128 + n], s = sinb[t * 128 + n];
    float rr = fmaf(rn, c, rh * s);
    rout[idx] = rr;

    float z = w0[hn] + wfull[idx];
    float u = -z;
    float sp = fmaxf(u, 0.0f) + log1pf(expf(-fabsf(u)));
    float w = -sp - 0.5f;
    wdout[idx] = expf(-expf(w));

    float a = sigmoidf_(a0[hn] + afull[idx]);
    int kvidx = t * KVN_DIM + (h >> 2) * 128 + n;
    float kfv = kfbuf[kvidx];
    float bbv = kkbuf[kvidx] * a;
    bbout[idx] = bbv;

    float p0 = rr * kfv * r_k[hn];
    float p1 = bbv * rr;
    float p2 = kfv * rr;
    blockReduceSum3(p0, p1, p2, red3);
    if (n == 0) {
        coef[t * H_NUM + h] = p0;
        c12[t * H_NUM + h] = make_float2(p1, p2);
    }
}

// ---------------- sequential scan (R8 version: warp-autonomous + depth-4 prefetch) ----------------
__global__ __launch_bounds__(32) void scan_kernel(const float* __restrict__ wdec,
                                                  const float* __restrict__ bb,
                                                  const float* __restrict__ kk,
                                                  const float* __restrict__ kf,
                                                  const float* __restrict__ rr,
                                                  const float* __restrict__ vf,
                                                  const float2* __restrict__ c12,
                                                  float* __restrict__ y) {
    const int h = blockIdx.x;
    const int rg = blockIdx.y;
    const int lane = threadIdx.x;
    const int kvh = h >> 2;

    const int hoff = h * 128 + lane * 4;
    const int koff = kvh * 128 + lane * 4;
    const int voff = kvh * 128 + rg * 4;
    float* py = y + h * 128 + rg * 4;

    ull S2[4][2];
#pragma unroll
    for (int i = 0; i < 4; i++) { S2[i][0] = 0ull; S2[i][1] = 0ull; }

    float4 Pw[4], Pb[4], Pr[4], Pk[4], Pf[4], Pv[4];
    float2 Pc[4];
#pragma unroll
    for (int d = 0; d < 4; d++) {
        size_t oH = (size_t)d * HN_DIM;
        size_t oKV = (size_t)d * KVN_DIM;
        Pw[d] = *(const float4*)&wdec[oH + hoff];
        Pb[d] = *(const float4*)&bb[oH + hoff];
        Pr[d] = *(const float4*)&rr[oH + hoff];
        Pk[d] = *(const float4*)&kk[oKV + koff];
        Pf[d] = *(const float4*)&kf[oKV + koff];
        Pv[d] = *(const float4*)&vf[oKV + voff];
        Pc[d] = c12[d * H_NUM + h];
    }

    for (int t = 0; t < T_LEN; t += 4) {
#pragma unroll
        for (int u = 0; u < 4; u++) {
            float4 w4 = Pw[u], b4 = Pb[u], r4 = Pr[u], k4 = Pk[u], f4 = Pf[u], v4 = Pv[u];
            float2 cc = Pc[u];

            int tn = t + u + 4;
            if (tn > T_LEN - 1) tn = T_LEN - 1;
            size_t oH = (size_t)tn * HN_DIM;
            size_t oKV = (size_t)tn * KVN_DIM;
            Pw[u] = *(const float4*)&wdec[oH + hoff];
            Pb[u] = *(const float4*)&bb[oH + hoff];
            Pr[u] = *(const float4*)&rr[oH + hoff];
            Pk[u] = *(const float4*)&kk[oKV + koff];
            Pf[u] = *(const float4*)&kf[oKV + koff];
            Pv[u] = *(const float4*)&vf[oKV + voff];
            Pc[u] = c12[tn * H_NUM + h];

            ull wA = pack2(w4.x, w4.y), wB = pack2(w4.z, w4.w);
            ull bA = pack2(b4.x, b4.y), bB = pack2(b4.z, b4.w);
            ull kA = pack2(k4.x, k4.y), kB = pack2(k4.z, k4.w);
            ull fA = pack2(f4.x, f4.y), fB = pack2(f4.z, f4.w);
            ull wrA = pack2(w4.x * r4.x, w4.y * r4.y);
            ull wrB = pack2(w4.z * r4.z, w4.w * r4.w);

            float sa[4], d1[4];
#pragma unroll
            for (int i = 0; i < 4; i++) {
                ull sdp = fma2_(S2[i][1], kB, mul2_(S2[i][0], kA));
                float2 su = unpack2(sdp);
                sa[i] = su.x + su.y;
                ull ddp = fma2_(S2[i][1], wrB, mul2_(S2[i][0], wrA));
                float2 du = unpack2(ddp);
                d1[i] = du.x + du.y;
            }

#pragma unroll
            for (int m = 16; m > 0; m >>= 1) {
                sa[0] += __shfl_xor_sync(0xffffffffu, sa[0], m);
                sa[1] += __shfl_xor_sync(0xffffffffu, sa[1], m);
                sa[2] += __shfl_xor_sync(0xffffffffu, sa[2], m);
                sa[3] += __shfl_xor_sync(0xffffffffu, sa[3], m);
                d1[0] += __shfl_xor_sync(0xffffffffu, d1[0], m);
                d1[1] += __shfl_xor_sync(0xffffffffu, d1[1], m);
                d1[2] += __shfl_xor_sync(0xffffffffu, d1[2], m);
                d1[3] += __shfl_xor_sync(0xffffffffu, d1[3], m);
            }
#pragma unroll
            for (int i = 0; i < 4; i++) sa[i] = -sa[i];

            if (lane == 0) {
                float4 yo;
                yo.x = fmaf(sa[0], cc.x, fmaf(v4.x, cc.y, d1[0]));
                yo.y = fmaf(sa[1], cc.x, fmaf(v4.y, cc.y, d1[1]));
                yo.z = fmaf(sa[2], cc.x, fmaf(v4.z, cc.y, d1[2]));
                yo.w = fmaf(sa[3], cc.x, fmaf(v4.w, cc.y, d1[3]));
                *(float4*)&py[(size_t)(t + u) * HN_DIM] = yo;
            }

            const float vv[4] = {v4.x, v4.y, v4.z, v4.w};
#pragma unroll
            for (int i = 0; i < 4; i++) {
                ull sai = pack2(sa[i], sa[i]);
                ull vvi = pack2(vv[i], vv[i]);
                S2[i][0] = fma2_(S2[i][0], wA, fma2_(sai, bA, mul2_(vvi, fA)));
                S2[i][1] = fma2_(S2[i][1], wB, fma2_(sai, bB, mul2_(vvi, fB)));
            }
        }
    }
}

// ---------------- launch ----------------
static float* symAddrF(const void* sym) {
    void* p = nullptr;
    cudaGetSymbolAddress(&p, sym);
    return (float*)p;
}
static float2* symAddrF2(const void* sym) {
    void* p = nullptr;
    cudaGetSymbolAddress(&p, sym);
    return (float2*)p;
}
static __nv_bfloat16* symAddrB(const void* sym) {
    void* p = nullptr;
    cudaGetSymbolAddress(&p, sym);
    return (__nv_bfloat16*)p;
}

extern "C" void kernel_launch(void* const* d_in, const int* in_sizes, int n_in,
                              void* d_out, int out_size) {
    const float* x = (const float*)d_in[0];
    const float* v_first = (const float*)d_in[1];
    const float* k_first = (const float*)d_in[2];
    const float* amask = (const float*)d_in[3];
    const float* cosb = (const float*)d_in[4];
    const float* sinb = (const float*)d_in[5];
    const float* w0 = (const float*)d_in[6];
    const float* w1 = (const float*)d_in[7];
    const float* w2 = (const float*)d_in[8];
    const float* a0 = (const float*)d_in[9];
    const float* a1 = (const float*)d_in[10];
    const float* a2 = (const float*)d_in[11];
    const float* v0 = (const float*)d_in[12];
    const float* v1 = (const float*)d_in[13];
    const float* v2 = (const float*)d_in[14];
    const float* k0 = (const float*)d_in[15];
    const float* k1 = (const float*)d_in[16];
    const float* k2 = (const float*)d_in[17];
    const float* g1 = (const float*)d_in[18];
    const float* g2 = (const float*)d_in[19];
    const float* r_k = (const float*)d_in[20];
    const float* r_norm_w = (const float*)d_in[21];
    const float* k_norm_w = (const float*)d_in[22];
    const float* W_r = (const float*)d_in[23];
    const float* W_k = (const float*)d_in[24];
    const float* W_v = (const float*)d_in[25];
    const float* W_o = (const float*)d_in[26];
    float* out = (float*)d_out;

    float* Ccat = symAddrF(g_Ccat);
    float* wfull = symAddrF(g_wfull);
    float* afull = symAddrF(g_afull);
    float* gfull = symAddrF(g_gfull);
    float* vmix = symAddrF(g_vmix);
    float* kmix = symAddrF(g_kmix);
    float* rrb = symAddrF(g_rr);
    float* kf = symAddrF(g_kf);
    float* vf = symAddrF(g_vf);
    float* kkb = symAddrF(g_kk);
    float* wd = symAddrF(g_wd);
    float* bbb = symAddrF(g_bb);
    float* coef = symAddrF(g_coef);
    float2* c12 = symAddrF2(g_c12);
    float* yb = symAddrF(g_y);
    __nv_bfloat16* Ap = symAddrB(g_Ap);
    __nv_bfloat16* Bp = symAddrB(g_Bp);

    // ---- stage 1 ----
    const int NTC2 = T_LEN * C_DIM / 2;
    splitAmask_kernel<<<(NTC2 + 255) / 256, 256>>>(x, amask, Ap, NTC2);

    const int NB2 = T_LEN * NCAT / 2;
    splitBcat_kernel<<<(NB2 + 255) / 256, 256>>>(W_r, W_k, W_v, w1, a1, v1, k1, g1, Bp, NB2);

    {
        dim3 grid((NCAT + 127) / 128, 2048 / 128);
        bf16_gemm_kernel<<<grid, 256>>>(Ap, Bp, Ccat, 2048, NCAT, 2048, NCAT, NCAT);
    }

    // ---- fused activations + stage-2 A splits ----
    const int NMIDS2 = T_LEN * NMID / 2;
    splitMids_kernel<<<(NMIDS2 + 255) / 256, 256>>>(Ccat, Ap, NMIDS2);

    // ---- stage 2: one fused B split + 5 GEMMs ----
    {
        const int n2 = 917504 / 2;
        splitB2_kernel<<<(n2 + 255) / 256, 256>>>(w2, a2, g2, v2, k2, Bp, n2);
    }
    auto gemm2 = [&](size_t aBase, size_t bBase, int K, float* C, int N) {
        dim3 grid((N + 127) / 128, 2048 / 128);
        bf16_gemm_kernel<<<grid, 256>>>(Ap + aBase, Bp + bBase, C, 2048, N, K, N, N);
    };
    gemm2(APW_BASE, BW_BASE, 160, wfull, 2048);
    gemm2(APA_BASE, BA_BASE, 96, afull, 2048);
    gemm2(APG_BASE, BG_BASE, 160, gfull, 2048);
    gemm2(APV_BASE, BV_BASE, 64, vmix, 512);
    gemm2(APK_BASE, BK_BASE, 64, kmix, 512);

    // ---- postprocess ----
    pp_kv_kernel<<<dim3(T_LEN, KVH_NUM), 128>>>(Ccat, kmix, vmix, k_first, v_first,
                                                k0, v0, k_norm_w, cosb, sinb,
                                                kf, vf, kkb);
    pp_h_kernel<<<dim3(T_LEN, H_NUM), 128>>>(Ccat, wfull, afull, w0, a0, kkb, kf,
                                             r_norm_w, cosb, sinb, r_k,
                                             rrb, wd, bbb, coef, c12);

    // ---- sequential scan: R8 config (512 warps, depth-4 prefetch) ----
    scan_kernel<<<dim3(H_NUM, 32), 32>>>(wd, bbb, kkb, kf, rrb, vf, c12, yb);

    // ---- fused merge + final A split ----
    const int NHN2 = T_LEN * HN_DIM / 2;
    mergeSplitA_kernel<<<(NHN2 + 255) / 256, 256>>>(yb, coef, vf, gfull, Ap, NHN2);

    // ---- final projection ----
    {
        int n2 = 2048 * 2048 / 2;
        splitB_kernel<<<(n2 + 255) / 256, 256>>>(W_o, Bp, 2048, 2048, 2048, 0, n2);
        dim3 grid(2048 / 128, 2048 / 128);
        bf16_gemm_kernel<<<grid, 256>>>(Ap, Bp, out, 2048, 2048, 2048, 2048, 2048);
    }
}

// round 14
// speedup vs baseline: 1.0940x; 1.0940x over previous
#include <cuda_runtime.h>
#include <cuda_bf16.h>
#include <cstdint>

#define T_LEN 2048
#define C_DIM 2048
#define H_NUM 16
#define N_DIM 128
#define KVH_NUM 4
#define HN_DIM 2048
#define KVN_DIM 512

// fused stage-1 output column offsets
#define OFF_XR 0
#define OFF_XK 2048
#define OFF_XV 2560
#define OFF_TW 3072
#define OFF_TA 3232
#define OFF_TV 3328
#define OFF_TK 3392
#define OFF_TG 3456
#define NCAT 3616
#define NMID 544

// stage-2 A' regions inside g_Ap (element offsets; K-tripled, row stride 3K)
#define APW_BASE 0
#define APA_BASE 983040
#define APG_BASE 1572864
#define APV_BASE 2555904
#define APK_BASE 2949120

// stage-2 B' regions inside g_Bp (element offsets; 3K rows x N)
#define BW_BASE 0
#define BA_BASE 983040
#define BG_BASE 1572864
#define BV_BASE 2555904
#define BK_BASE 2654208

// ---------------- scratch ----------------
__device__ float g_Ccat[(size_t)T_LEN * NCAT];
__device__ float g_wfull[T_LEN * HN_DIM];
__device__ float g_afull[T_LEN * HN_DIM];
__device__ float g_gfull[T_LEN * HN_DIM];
__device__ float g_vmix[T_LEN * KVN_DIM];
__device__ float g_kmix[T_LEN * KVN_DIM];
__device__ float g_rr[T_LEN * HN_DIM];
__device__ float g_kf[T_LEN * KVN_DIM];
__device__ float g_vf[T_LEN * KVN_DIM];
__device__ float g_kk[T_LEN * KVN_DIM];
__device__ float g_wd[T_LEN * HN_DIM];
__device__ float g_bb[T_LEN * HN_DIM];
__device__ float g_coef[T_LEN * H_NUM];
__device__ float2 g_c12[T_LEN * H_NUM];
__device__ float g_y[T_LEN * HN_DIM];

__device__ __nv_bfloat16 g_Ap[(size_t)2048 * 3 * 2048];
__device__ __nv_bfloat16 g_Bp[(size_t)3 * 2048 * NCAT];

// ---------------- helpers ----------------
__device__ __forceinline__ float sigmoidf_(float x) { return 1.0f / (1.0f + expf(-x)); }

// packed f32x2 ops (sm_103a)
typedef unsigned long long ull;
__device__ __forceinline__ ull pack2(float x, float y) {
    ull r;
    asm("mov.b64 %0, {%1, %2};" : "=l"(r) : "f"(x), "f"(y));
    return r;
}
__device__ __forceinline__ float2 unpack2(ull v) {
    float x, y;
    asm("mov.b64 {%0, %1}, %2;" : "=f"(x), "=f"(y) : "l"(v));
    return make_float2(x, y);
}
__device__ __forceinline__ ull fma2_(ull a, ull b, ull c) {
    ull d;
    asm("fma.rn.f32x2 %0, %1, %2, %3;" : "=l"(d) : "l"(a), "l"(b), "l"(c));
    return d;
}
__device__ __forceinline__ ull mul2_(ull a, ull b) {
    ull d;
    asm("mul.rn.f32x2 %0, %1, %2;" : "=l"(d) : "l"(a), "l"(b));
    return d;
}

__device__ __forceinline__ uint32_t packsplit_hi(float a, float b) {
    __nv_bfloat162 h = __floats2bfloat162_rn(a, b);
    return *(uint32_t*)&h;
}
__device__ __forceinline__ uint32_t packsplit_lo(float a, float b, uint32_t hipack) {
    __nv_bfloat162* hp = (__nv_bfloat162*)&hipack;
    float ra = a - __bfloat162float(hp->x);
    float rb = b - __bfloat162float(hp->y);
    __nv_bfloat162 l = __floats2bfloat162_rn(ra, rb);
    return *(uint32_t*)&l;
}

// ---------------- split conversions (R8 K-tripled layouts) ----------------
__global__ void splitAmask_kernel(const float* __restrict__ x, const float* __restrict__ mask,
                                  __nv_bfloat16* __restrict__ Ap, int n2) {
    int i = blockIdx.x * blockDim.x + threadIdx.x;
    if (i >= n2) return;
    int i2 = i * 2;
    int r = i2 >> 11, c = i2 & 2047;
    float2 xv = *(const float2*)&x[i2];
    float m = mask[r];
    float v0 = xv.x * m, v1 = xv.y * m;
    uint32_t hi = packsplit_hi(v0, v1);
    uint32_t lo = packsplit_lo(v0, v1, hi);
    size_t base = (size_t)r * 6144 + c;
    *(uint32_t*)&Ap[base] = hi;
    *(uint32_t*)&Ap[base + 2048] = lo;
    *(uint32_t*)&Ap[base + 4096] = hi;
}

__global__ void splitBcat_kernel(const float* __restrict__ W_r, const float* __restrict__ W_k,
                                 const float* __restrict__ W_v, const float* __restrict__ w1,
                                 const float* __restrict__ a1, const float* __restrict__ v1,
                                 const float* __restrict__ k1, const float* __restrict__ g1,
                                 __nv_bfloat16* __restrict__ Bp, int n2) {
    int i = blockIdx.x * blockDim.x + threadIdx.x;
    if (i >= n2) return;
    int i2 = i * 2;
    int r = i2 / NCAT, c = i2 - r * NCAT;
    const float* src;
    int off, ncols;
    if (c < 2048) { src = W_r; off = OFF_XR; ncols = 2048; }
    else if (c < 2560) { src = W_k; off = OFF_XK; ncols = 512; }
    else if (c < 3072) { src = W_v; off = OFF_XV; ncols = 512; }
    else if (c < 3232) { src = w1; off = OFF_TW; ncols = 160; }
    else if (c < 3328) { src = a1; off = OFF_TA; ncols = 96; }
    else if (c < 3392) { src = v1; off = OFF_TV; ncols = 64; }
    else if (c < 3456) { src = k1; off = OFF_TK; ncols = 64; }
    else { src = g1; off = OFF_TG; ncols = 160; }
    float2 xv = *(const float2*)&src[(size_t)r * ncols + (c - off)];
    uint32_t hi = packsplit_hi(xv.x, xv.y);
    uint32_t lo = packsplit_lo(xv.x, xv.y, hi);
    size_t base = (size_t)r * NCAT + c;
    *(uint32_t*)&Bp[base] = hi;
    *(uint32_t*)&Bp[base + (size_t)2048 * NCAT] = hi;
    *(uint32_t*)&Bp[base + (size_t)4096 * NCAT] = lo;
}

__global__ void splitB_kernel(const float* __restrict__ B, __nv_bfloat16* __restrict__ Bp,
                              int K, int Ncols, int ldB, int colOff, int n2) {
    int i = blockIdx.x * blockDim.x + threadIdx.x;
    if (i >= n2) return;
    int i2 = i * 2;
    int r = i2 / Ncols, c = i2 - r * Ncols;
    float2 xv = *(const float2*)&B[i2];
    uint32_t hi = packsplit_hi(xv.x, xv.y);
    uint32_t lo = packsplit_lo(xv.x, xv.y, hi);
    size_t base = (size_t)r * ldB + colOff + c;
    *(uint32_t*)&Bp[base] = hi;
    *(uint32_t*)&Bp[base + (size_t)K * ldB] = hi;
    *(uint32_t*)&Bp[base + (size_t)2 * K * ldB] = lo;
}

__global__ void splitB2_kernel(const float* __restrict__ w2, const float* __restrict__ a2,
                               const float* __restrict__ g2, const float* __restrict__ v2,
                               const float* __restrict__ k2, __nv_bfloat16* __restrict__ Bp,
                               int n2) {
    int i = blockIdx.x * blockDim.x + threadIdx.x;
    if (i >= n2) return;
    int i2 = i * 2;
    const float* src;
    int K, N, local;
    size_t base;
    if (i2 < 327680) { src = w2; K = 160; N = 2048; base = BW_BASE; local = i2; }
    else if (i2 < 524288) { src = a2; K = 96; N = 2048; base = BA_BASE; local = i2 - 327680; }
    else if (i2 < 851968) { src = g2; K = 160; N = 2048; base = BG_BASE; local = i2 - 524288; }
    else if (i2 < 884736) { src = v2; K = 64; N = 512; base = BV_BASE; local = i2 - 851968; }
    else { src = k2; K = 64; N = 512; base = BK_BASE; local = i2 - 884736; }
    float2 xv = *(const float2*)&src[local];
    uint32_t hi = packsplit_hi(xv.x, xv.y);
    uint32_t lo = packsplit_lo(xv.x, xv.y, hi);
    size_t off = base + (size_t)local;
    *(uint32_t*)&Bp[off] = hi;
    *(uint32_t*)&Bp[off + (size_t)K * N] = hi;
    *(uint32_t*)&Bp[off + (size_t)2 * K * N] = lo;
}

// ---------------- fused act + stage-2 A-split from Ccat ----------------
__global__ void splitMids_kernel(const float* __restrict__ Ccat, __nv_bfloat16* __restrict__ Ap,
                                 int n2) {
    int i = blockIdx.x * blockDim.x + threadIdx.x;
    if (i >= n2) return;
    int i2 = i * 2;
    int t = i2 / NMID, c = i2 - t * NMID;
    const float* src = &Ccat[(size_t)t * NCAT + OFF_TW];
    float v0 = src[c], v1 = src[c + 1];
    int K, lc;
    size_t base;
    if (c < 160) {
        v0 = tanhf(v0); v1 = tanhf(v1);
        K = 160; base = APW_BASE; lc = c;
    } else if (c < 256) {
        K = 96; base = APA_BASE; lc = c - 160;
    } else if (c < 320) {
        K = 64; base = APV_BASE; lc = c - 256;
    } else if (c < 384) {
        K = 64; base = APK_BASE; lc = c - 320;
    } else {
        v0 = sigmoidf_(v0); v1 = sigmoidf_(v1);
        K = 160; base = APG_BASE; lc = c - 384;
    }
    uint32_t hi = packsplit_hi(v0, v1);
    uint32_t lo = packsplit_lo(v0, v1, hi);
    size_t off = base + (size_t)t * (3 * K) + lc;
    *(uint32_t*)&Ap[off] = hi;
    *(uint32_t*)&Ap[off + K] = lo;
    *(uint32_t*)&Ap[off + 2 * K] = hi;
}

// ---------------- fused merge + final A-split ----------------
__global__ void mergeSplitA_kernel(const float* __restrict__ y, const float* __restrict__ coef,
                                   const float* __restrict__ vf, const float* __restrict__ gbuf,
                                   __nv_bfloat16* __restrict__ Ap, int n2) {
    int i = blockIdx.x * blockDim.x + threadIdx.x;
    if (i >= n2) return;
    int i2 = i * 2;
    int t = i2 >> 11, hn = i2 & 2047;
    int h = hn >> 7, nn = hn & 127;
    float cf = coef[t * H_NUM + h];
    const float* vp = &vf[t * KVN_DIM + (h >> 2) * 128 + nn];
    float2 yv = *(const float2*)&y[i2];
    float2 gv = *(const float2*)&gbuf[i2];
    float v0 = (yv.x + cf * vp[0]) * gv.x;
    float v1 = (yv.y + cf * vp[1]) * gv.y;
    uint32_t hi = packsplit_hi(v0, v1);
    uint32_t lo = packsplit_lo(v0, v1, hi);
    size_t base = (size_t)t * 6144 + hn;
    *(uint32_t*)&Ap[base] = hi;
    *(uint32_t*)&Ap[base + 2048] = lo;
    *(uint32_t*)&Ap[base + 4096] = hi;
}

// ---------------- bf16 tensor-core GEMM, 3-stage cp.async pipeline (R8) ----------------
#define LDA_S 40
#define LDB_S 136
#define NSTAGE 3

__global__ __launch_bounds__(256) void bf16_gemm_kernel(
    const __nv_bfloat16* __restrict__ A, const __nv_bfloat16* __restrict__ B,
    float* __restrict__ C, int M, int N, int K3, int ldB, int ldC) {
    __shared__ __align__(16) __nv_bfloat16 As[NSTAGE][128 * LDA_S];
    __shared__ __align__(16) __nv_bfloat16 Bs[NSTAGE][32 * LDB_S];

    const int tid = threadIdx.x;
    const int bm = blockIdx.y * 128;
    const int bn = blockIdx.x * 128;
    const int warp = tid >> 5;
    const int lane = tid & 31;
    const int wm = warp & 3;
    const int wn = warp >> 2;

    const int ar = tid >> 2;
    const int ac = (tid & 3) * 8;
    const int br = tid >> 4;
    const int bc = (tid & 15) * 8;
    const int bsz = ((bn + bc) < N) ? 16 : 0;

    float c[2][8][4];
#pragma unroll
    for (int mi = 0; mi < 2; mi++)
#pragma unroll
        for (int ni = 0; ni < 8; ni++)
#pragma unroll
            for (int q = 0; q < 4; q++) c[mi][ni][q] = 0.0f;

    const int KT = K3 >> 5;

    auto load_stage = [&](int st, int kt) {
        int k0 = kt * 32;
#pragma unroll
        for (int it = 0; it < 2; it++) {
            const __nv_bfloat16* src = A + (size_t)(bm + ar + it * 64) * K3 + k0 + ac;
            uint32_t dst = (uint32_t)__cvta_generic_to_shared(&As[st][(ar + it * 64) * LDA_S + ac]);
            asm volatile("cp.async.ca.shared.global [%0], [%1], 16;\n" ::"r"(dst), "l"(src));
        }
#pragma unroll
        for (int it = 0; it < 2; it++) {
            const __nv_bfloat16* src = B + (size_t)(k0 + br + it * 16) * ldB + bn + bc;
            uint32_t dst = (uint32_t)__cvta_generic_to_shared(&Bs[st][(br + it * 16) * LDB_S + bc]);
            asm volatile("cp.async.ca.shared.global [%0], [%1], 16, %2;\n" ::"r"(dst), "l"(src),
                         "r"(bsz));
        }
        asm volatile("cp.async.commit_group;\n");
    };

    auto compute_stage = [&](int st) {
#pragma unroll
        for (int kk = 0; kk < 32; kk += 16) {
            uint32_t af[2][4];
#pragma unroll
            for (int mi = 0; mi < 2; mi++) {
                uint32_t addr = (uint32_t)__cvta_generic_to_shared(
                    &As[st][(wm * 32 + mi * 16 + (lane & 15)) * LDA_S + kk + (lane >> 4) * 8]);
                asm volatile("ldmatrix.sync.aligned.m8n8.x4.shared.b16 {%0,%1,%2,%3}, [%4];\n"
                             : "=r"(af[mi][0]), "=r"(af[mi][1]), "=r"(af[mi][2]), "=r"(af[mi][3])
                             : "r"(addr));
            }
            uint32_t bfr[8][2];
#pragma unroll
            for (int p = 0; p < 4; p++) {
                uint32_t addr = (uint32_t)__cvta_generic_to_shared(
                    &Bs[st][(kk + (lane & 15)) * LDB_S + wn * 64 + p * 16 + (lane >> 4) * 8]);
                uint32_t b0, b1, b2, b3;
                asm volatile("ldmatrix.sync.aligned.m8n8.x4.trans.shared.b16 {%0,%1,%2,%3}, [%4];\n"
                             : "=r"(b0), "=r"(b1), "=r"(b2), "=r"(b3)
                             : "r"(addr));
                bfr[p * 2][0] = b0;
                bfr[p * 2][1] = b1;
                bfr[p * 2 + 1][0] = b2;
                bfr[p * 2 + 1][1] = b3;
            }
#pragma unroll
            for (int mi = 0; mi < 2; mi++)
#pragma unroll
                for (int ni = 0; ni < 8; ni++) {
                    asm volatile(
                        "mma.sync.aligned.m16n8k16.row.col.f32.bf16.bf16.f32 "
                        "{%0,%1,%2,%3}, {%4,%5,%6,%7}, {%8,%9}, {%0,%1,%2,%3};\n"
                        : "+f"(c[mi][ni][0]), "+f"(c[mi][ni][1]), "+f"(c[mi][ni][2]),
                          "+f"(c[mi][ni][3])
                        : "r"(af[mi][0]), "r"(af[mi][1]), "r"(af[mi][2]), "r"(af[mi][3]),
                          "r"(bfr[ni][0]), "r"(bfr[ni][1]));
                }
        }
    };

    load_stage(0, 0);
    if (KT > 1) load_stage(1, 1);
    for (int kt = 0; kt < KT; kt++) {
        if (kt + 2 < KT) {
            load_stage((kt + 2) % NSTAGE, kt + 2);
            asm volatile("cp.async.wait_group 2;\n");
        } else if (kt + 1 < KT) {
            asm volatile("cp.async.wait_group 1;\n");
        } else {
            asm volatile("cp.async.wait_group 0;\n");
        }
        __syncthreads();
        compute_stage(kt % NSTAGE);
        __syncthreads();
    }

#pragma unroll
    for (int mi = 0; mi < 2; mi++) {
        int row = bm + wm * 32 + mi * 16 + (lane >> 2);
#pragma unroll
        for (int ni = 0; ni < 8; ni++) {
            int col = bn + wn * 64 + ni * 8 + (lane & 3) * 2;
            if (col < N) {
                C[(size_t)row * ldC + col] = c[mi][ni][0];
                C[(size_t)row * ldC + col + 1] = c[mi][ni][1];
                C[(size_t)(row + 8) * ldC + col] = c[mi][ni][2];
                C[(size_t)(row + 8) * ldC + col + 1] = c[mi][ni][3];
            }
        }
    }
}

// ---------------- FUSED postprocess: one block per t, 512 threads (4 groups) ----------------
// Phase A: group g handles kvh=g (k-norm/rope/mix, v-mix, kk); kf/kk parked in smem.
// Phase B: 4 iterations; iteration it: group g handles head h=it*4+g (kvh==it),
// reading kk/kf from smem instead of global. All groups execute identical reduction
// sequences, so block-wide __syncthreads barriers are safe.
__global__ __launch_bounds__(512) void pp_fused_kernel(
    const float* __restrict__ Ccat, const float* __restrict__ kmix,
    const float* __restrict__ vmix, const float* __restrict__ k_first,
    const float* __restrict__ v_first, const float* __restrict__ k0,
    const float* __restrict__ v0, const float* __restrict__ knw,
    const float* __restrict__ wfull, const float* __restrict__ afull,
    const float* __restrict__ w0, const float* __restrict__ a0,
    const float* __restrict__ rnw, const float* __restrict__ cosb,
    const float* __restrict__ sinb, const float* __restrict__ r_k,
    float* __restrict__ kf, float* __restrict__ vfout, float* __restrict__ kkout,
    float* __restrict__ rout, float* __restrict__ wdout, float* __restrict__ bbout,
    float* __restrict__ coef, float2* __restrict__ c12) {
    const int t = blockIdx.x;
    const int tid = threadIdx.x;
    const int g = tid >> 7;        // group 0..3
    const int wg = tid & 127;      // index within group
    const int lane = tid & 31;
    const int warp = tid >> 5;     // 0..15

    __shared__ float stage[512];   // phase A: kn staging; phase B: rn staging
    __shared__ float skf[512], skk[512];
    __shared__ float red1[16];
    __shared__ float red3[16][3];

    // group-scoped reduce (128 threads), block-wide barriers (uniform across groups)
    auto groupReduce = [&](float v) -> float {
#pragma unroll
        for (int m = 16; m > 0; m >>= 1) v += __shfl_xor_sync(0xffffffffu, v, m);
        __syncthreads();
        if (lane == 0) red1[warp] = v;
        __syncthreads();
        int b = g * 4;
        return red1[b] + red1[b + 1] + red1[b + 2] + red1[b + 3];
    };
    auto groupReduce3 = [&](float& a, float& b, float& c) {
#pragma unroll
        for (int m = 16; m > 0; m >>= 1) {
            a += __shfl_xor_sync(0xffffffffu, a, m);
            b += __shfl_xor_sync(0xffffffffu, b, m);
            c += __shfl_xor_sync(0xffffffffu, c, m);
        }
        __syncthreads();
        if (lane == 0) {
            red3[warp][0] = a;
            red3[warp][1] = b;
            red3[warp][2] = c;
        }
        __syncthreads();
        int q = g * 4;
        a = red3[q][0] + red3[q + 1][0] + red3[q + 2][0] + red3[q + 3][0];
        b = red3[q][1] + red3[q + 1][1] + red3[q + 2][1] + red3[q + 3][1];
        c = red3[q][2] + red3[q + 1][2] + red3[q + 2][2] + red3[q + 3][2];
    };

    const float cs_c = cosb[t * 128 + wg];
    const float cs_s = sinb[t * 128 + wg];

    // ---------- Phase A: kvh = g ----------
    {
        const int idx = t * KVN_DIM + g * 128 + wg;
        const size_t cidx = (size_t)t * NCAT + g * 128 + wg;

        float k = Ccat[cidx + OFF_XK];
        float ss = groupReduce(k * k);
        float kn = knw[wg] * k * rsqrtf(ss * (1.0f / 128.0f) + 1e-6f);
        stage[tid] = kn;
        __syncthreads();
        float rh = (wg < 64) ? -stage[g * 128 + wg + 64] : stage[g * 128 + wg - 64];
        float kr = fmaf(kn, cs_c, rh * cs_s);

        float kfv = kr + (k_first[idx] - kr) * sigmoidf_(k0[g * 128 + wg] + kmix[idx]);
        float vv = Ccat[cidx + OFF_XV];
        float vfv = vv + (v_first[idx] - vv) * sigmoidf_(v0[g * 128 + wg] + vmix[idx]);

        float nrm2 = groupReduce(kfv * kfv);
        float denom = fmaxf(sqrtf(nrm2), 1e-12f);
        float kkv = kfv / denom;

        kf[idx] = kfv;
        vfout[idx] = vfv;
        kkout[idx] = kkv;
        skf[tid] = kfv;
        skk[tid] = kkv;
    }
    __syncthreads();

    // ---------- Phase B: 4 iterations; head h = it*4 + g, kvh = it ----------
#pragma unroll
    for (int it = 0; it < 4; it++) {
        const int h = it * 4 + g;
        const int hn = h * 128 + wg;
        const int idx = t * HN_DIM + hn;

        float r = Ccat[(size_t)t * NCAT + OFF_XR + hn];
        float ss = groupReduce(r * r);
        float rn = rnw[wg] * r * rsqrtf(ss * (1.0f / 128.0f) + 1e-6f);
        __syncthreads();  // protect stage from previous iteration's reads
        stage[tid] = rn;
        __syncthreads();
        float rh = (wg < 64) ? -stage[g * 128 + wg + 64] : stage[g * 128 + wg - 64];
        float rr = fmaf(rn, cs_c, rh * cs_s);
        rout[idx] = rr;

        float z = w0[hn] + wfull[idx];
        float u = -z;
        float sp = fmaxf(u, 0.0f) + log1pf(expf(-fabsf(u)));
        float w = -sp - 0.5f;
        wdout[idx] = expf(-expf(w));

        float a = sigmoidf_(a0[hn] + afull[idx]);
        float kfv = skf[it * 128 + wg];
        float bbv = skk[it * 128 + wg] * a;
        bbout[idx] = bbv;

        float p0 = rr * kfv * r_k[hn];
        float p1 = bbv * rr;
        float p2 = kfv * rr;
        groupReduce3(p0, p1, p2);
        if (wg == 0) {
            coef[t * H_NUM + h] = p0;
            c12[t * H_NUM + h] = make_float2(p1, p2);
        }
    }
}

// ---------------- sequential scan (R8: warp-autonomous + depth-4 prefetch) ----------------
__global__ __launch_bounds__(32) void scan_kernel(const float* __restrict__ wdec,
                                                  const float* __restrict__ bb,
                                                  const float* __restrict__ kk,
                                                  const float* __restrict__ kf,
                                                  const float* __restrict__ rr,
                                                  const float* __restrict__ vf,
                                                  const float2* __restrict__ c12,
                                                  float* __restrict__ y) {
    const int h = blockIdx.x;
    const int rg = blockIdx.y;
    const int lane = threadIdx.x;
    const int kvh = h >> 2;

    const int hoff = h * 128 + lane * 4;
    const int koff = kvh * 128 + lane * 4;
    const int voff = kvh * 128 + rg * 4;
    float* py = y + h * 128 + rg * 4;

    ull S2[4][2];
#pragma unroll
    for (int i = 0; i < 4; i++) { S2[i][0] = 0ull; S2[i][1] = 0ull; }

    float4 Pw[4], Pb[4], Pr[4], Pk[4], Pf[4], Pv[4];
    float2 Pc[4];
#pragma unroll
    for (int d = 0; d < 4; d++) {
        size_t oH = (size_t)d * HN_DIM;
        size_t oKV = (size_t)d * KVN_DIM;
        Pw[d] = *(const float4*)&wdec[oH + hoff];
        Pb[d] = *(const float4*)&bb[oH + hoff];
        Pr[d] = *(const float4*)&rr[oH + hoff];
        Pk[d] = *(const float4*)&kk[oKV + koff];
        Pf[d] = *(const float4*)&kf[oKV + koff];
        Pv[d] = *(const float4*)&vf[oKV + voff];
        Pc[d] = c12[d * H_NUM + h];
    }

    for (int t = 0; t < T_LEN; t += 4) {
#pragma unroll
        for (int u = 0; u < 4; u++) {
            float4 w4 = Pw[u], b4 = Pb[u], r4 = Pr[u], k4 = Pk[u], f4 = Pf[u], v4 = Pv[u];
            float2 cc = Pc[u];

            int tn = t + u + 4;
            if (tn > T_LEN - 1) tn = T_LEN - 1;
            size_t oH = (size_t)tn * HN_DIM;
            size_t oKV = (size_t)tn * KVN_DIM;
            Pw[u] = *(const float4*)&wdec[oH + hoff];
            Pb[u] = *(const float4*)&bb[oH + hoff];
            Pr[u] = *(const float4*)&rr[oH + hoff];
            Pk[u] = *(const float4*)&kk[oKV + koff];
            Pf[u] = *(const float4*)&kf[oKV + koff];
            Pv[u] = *(const float4*)&vf[oKV + voff];
            Pc[u] = c12[tn * H_NUM + h];

            ull wA = pack2(w4.x, w4.y), wB = pack2(w4.z, w4.w);
            ull bA = pack2(b4.x, b4.y), bB = pack2(b4.z, b4.w);
            ull kA = pack2(k4.x, k4.y), kB = pack2(k4.z, k4.w);
            ull fA = pack2(f4.x, f4.y), fB = pack2(f4.z, f4.w);
            ull wrA = pack2(w4.x * r4.x, w4.y * r4.y);
            ull wrB = pack2(w4.z * r4.z, w4.w * r4.w);

            float sa[4], d1[4];
#pragma unroll
            for (int i = 0; i < 4; i++) {
                ull sdp = fma2_(S2[i][1], kB, mul2_(S2[i][0], kA));
                float2 su = unpack2(sdp);
                sa[i] = su.x + su.y;
                ull ddp = fma2_(S2[i][1], wrB, mul2_(S2[i][0], wrA));
                float2 du = unpack2(ddp);
                d1[i] = du.x + du.y;
            }

#pragma unroll
            for (int m = 16; m > 0; m >>= 1) {
                sa[0] += __shfl_xor_sync(0xffffffffu, sa[0], m);
                sa[1] += __shfl_xor_sync(0xffffffffu, sa[1], m);
                sa[2] += __shfl_xor_sync(0xffffffffu, sa[2], m);
                sa[3] += __shfl_xor_sync(0xffffffffu, sa[3], m);
                d1[0] += __shfl_xor_sync(0xffffffffu, d1[0], m);
                d1[1] += __shfl_xor_sync(0xffffffffu, d1[1], m);
                d1[2] += __shfl_xor_sync(0xffffffffu, d1[2], m);
                d1[3] += __shfl_xor_sync(0xffffffffu, d1[3], m);
            }
#pragma unroll
            for (int i = 0; i < 4; i++) sa[i] = -sa[i];

            if (lane == 0) {
                float4 yo;
                yo.x = fmaf(sa[0], cc.x, fmaf(v4.x, cc.y, d1[0]));
                yo.y = fmaf(sa[1], cc.x, fmaf(v4.y, cc.y, d1[1]));
                yo.z = fmaf(sa[2], cc.x, fmaf(v4.z, cc.y, d1[2]));
                yo.w = fmaf(sa[3], cc.x, fmaf(v4.w, cc.y, d1[3]));
                *(float4*)&py[(size_t)(t + u) * HN_DIM] = yo;
            }

            const float vv[4] = {v4.x, v4.y, v4.z, v4.w};
#pragma unroll
            for (int i = 0; i < 4; i++) {
                ull sai = pack2(sa[i], sa[i]);
                ull vvi = pack2(vv[i], vv[i]);
                S2[i][0] = fma2_(S2[i][0], wA, fma2_(sai, bA, mul2_(vvi, fA)));
                S2[i][1] = fma2_(S2[i][1], wB, fma2_(sai, bB, mul2_(vvi, fB)));
            }
        }
    }
}

// ---------------- launch ----------------
static float* symAddrF(const void* sym) {
    void* p = nullptr;
    cudaGetSymbolAddress(&p, sym);
    return (float*)p;
}
static float2* symAddrF2(const void* sym) {
    void* p = nullptr;
    cudaGetSymbolAddress(&p, sym);
    return (float2*)p;
}
static __nv_bfloat16* symAddrB(const void* sym) {
    void* p = nullptr;
    cudaGetSymbolAddress(&p, sym);
    return (__nv_bfloat16*)p;
}

extern "C" void kernel_launch(void* const* d_in, const int* in_sizes, int n_in,
                              void* d_out, int out_size) {
    const float* x = (const float*)d_in[0];
    const float* v_first = (const float*)d_in[1];
    const float* k_first = (const float*)d_in[2];
    const float* amask = (const float*)d_in[3];
    const float* cosb = (const float*)d_in[4];
    const float* sinb = (const float*)d_in[5];
    const float* w0 = (const float*)d_in[6];
    const float* w1 = (const float*)d_in[7];
    const float* w2 = (const float*)d_in[8];
    const float* a0 = (const float*)d_in[9];
    const float* a1 = (const float*)d_in[10];
    const float* a2 = (const float*)d_in[11];
    const float* v0 = (const float*)d_in[12];
    const float* v1 = (const float*)d_in[13];
    const float* v2 = (const float*)d_in[14];
    const float* k0 = (const float*)d_in[15];
    const float* k1 = (const float*)d_in[16];
    const float* k2 = (const float*)d_in[17];
    const float* g1 = (const float*)d_in[18];
    const float* g2 = (const float*)d_in[19];
    const float* r_k = (const float*)d_in[20];
    const float* r_norm_w = (const float*)d_in[21];
    const float* k_norm_w = (const float*)d_in[22];
    const float* W_r = (const float*)d_in[23];
    const float* W_k = (const float*)d_in[24];
    const float* W_v = (const float*)d_in[25];
    const float* W_o = (const float*)d_in[26];
    float* out = (float*)d_out;

    float* Ccat = symAddrF(g_Ccat);
    float* wfull = symAddrF(g_wfull);
    float* afull = symAddrF(g_afull);
    float* gfull = symAddrF(g_gfull);
    float* vmix = symAddrF(g_vmix);
    float* kmix = symAddrF(g_kmix);
    float* rrb = symAddrF(g_rr);
    float* kf = symAddrF(g_kf);
    float* vf = symAddrF(g_vf);
    float* kkb = symAddrF(g_kk);
    float* wd = symAddrF(g_wd);
    float* bbb = symAddrF(g_bb);
    float* coef = symAddrF(g_coef);
    float2* c12 = symAddrF2(g_c12);
    float* yb = symAddrF(g_y);
    __nv_bfloat16* Ap = symAddrB(g_Ap);
    __nv_bfloat16* Bp = symAddrB(g_Bp);

    // ---- stage 1 ----
    const int NTC2 = T_LEN * C_DIM / 2;
    splitAmask_kernel<<<(NTC2 + 255) / 256, 256>>>(x, amask, Ap, NTC2);

    const int NB2 = T_LEN * NCAT / 2;
    splitBcat_kernel<<<(NB2 + 255) / 256, 256>>>(W_r, W_k, W_v, w1, a1, v1, k1, g1, Bp, NB2);

    {
        dim3 grid((NCAT + 127) / 128, 2048 / 128);
        bf16_gemm_kernel<<<grid, 256>>>(Ap, Bp, Ccat, 2048, NCAT, 6144, NCAT, NCAT);
    }

    // ---- fused activations + stage-2 A splits ----
    const int NMIDS2 = T_LEN * NMID / 2;
    splitMids_kernel<<<(NMIDS2 + 255) / 256, 256>>>(Ccat, Ap, NMIDS2);

    // ---- stage 2: one fused B split + 5 GEMMs ----
    {
        const int n2 = 917504 / 2;
        splitB2_kernel<<<(n2 + 255) / 256, 256>>>(w2, a2, g2, v2, k2, Bp, n2);
    }
    auto gemm2 = [&](size_t aBase, size_t bBase, int K, float* C, int N) {
        dim3 grid((N + 127) / 128, 2048 / 128);
        bf16_gemm_kernel<<<grid, 256>>>(Ap + aBase, Bp + bBase, C, 2048, N, 3 * K, N, N);
    };
    gemm2(APW_BASE, BW_BASE, 160, wfull, 2048);
    gemm2(APA_BASE, BA_BASE, 96, afull, 2048);
    gemm2(APG_BASE, BG_BASE, 160, gfull, 2048);
    gemm2(APV_BASE, BV_BASE, 64, vmix, 512);
    gemm2(APK_BASE, BK_BASE, 64, kmix, 512);

    // ---- FUSED postprocess (pp_kv + pp_h in one kernel) ----
    pp_fused_kernel<<<T_LEN, 512>>>(Ccat, kmix, vmix, k_first, v_first, k0, v0, k_norm_w,
                                    wfull, afull, w0, a0, r_norm_w, cosb, sinb, r_k,
                                    kf, vf, kkb, rrb, wd, bbb, coef, c12);

    // ---- sequential scan: R8 config (512 warps, depth-4 prefetch) ----
    scan_kernel<<<dim3(H_NUM, 32), 32>>>(wd, bbb, kkb, kf, rrb, vf, c12, yb);

    // ---- fused merge + final A split ----
    const int NHN2 = T_LEN * HN_DIM / 2;
    mergeSplitA_kernel<<<(NHN2 + 255) / 256, 256>>>(yb, coef, vf, gfull, Ap, NHN2);

    // ---- final projection ----
    {
        int n2 = 2048 * 2048 / 2;
        splitB_kernel<<<(n2 + 255) / 256, 256>>>(W_o, Bp, 2048, 2048, 2048, 0, n2);
        dim3 grid(2048 / 128, 2048 / 128);
        bf16_gemm_kernel<<<grid, 256>>>(Ap, Bp, out, 2048, 2048, 6144, 2048, 2048);
    }
}

// round 15
// speedup vs baseline: 1.1238x; 1.0272x over previous
#include <cuda_runtime.h>
#include <cuda_bf16.h>
#include <cstdint>

#define T_LEN 2048
#define C_DIM 2048
#define H_NUM 16
#define N_DIM 128
#define KVH_NUM 4
#define HN_DIM 2048
#define KVN_DIM 512

// fused stage-1 output column offsets
#define OFF_XR 0
#define OFF_XK 2048
#define OFF_XV 2560
#define OFF_TW 3072
#define OFF_TA 3232
#define OFF_TV 3328
#define OFF_TK 3392
#define OFF_TG 3456
#define NCAT 3616
#define NMID 544

// stage-2 A' regions inside g_Ap (element offsets; K-tripled, row stride 3K)
#define APW_BASE 0
#define APA_BASE 983040
#define APG_BASE 1572864
#define APV_BASE 2555904
#define APK_BASE 2949120

// stage-2 B' regions inside g_Bp (element offsets; 3K rows x N)
#define BW_BASE 0
#define BA_BASE 983040
#define BG_BASE 1572864
#define BV_BASE 2555904
#define BK_BASE 2654208
// W_o B' region (private; avoids racing stage-2 reads when split runs on side stream)
#define BWO_BASE 4194304

// ---------------- scratch ----------------
__device__ float g_Ccat[(size_t)T_LEN * NCAT];
__device__ float g_wfull[T_LEN * HN_DIM];
__device__ float g_afull[T_LEN * HN_DIM];
__device__ float g_gfull[T_LEN * HN_DIM];
__device__ float g_vmix[T_LEN * KVN_DIM];
__device__ float g_kmix[T_LEN * KVN_DIM];
__device__ float g_rr[T_LEN * HN_DIM];
__device__ float g_kf[T_LEN * KVN_DIM];
__device__ float g_vf[T_LEN * KVN_DIM];
__device__ float g_kk[T_LEN * KVN_DIM];
__device__ float g_wd[T_LEN * HN_DIM];
__device__ float g_bb[T_LEN * HN_DIM];
__device__ float g_coef[T_LEN * H_NUM];
__device__ float2 g_c12[T_LEN * H_NUM];
__device__ float g_y[T_LEN * HN_DIM];

__device__ __nv_bfloat16 g_Ap[(size_t)2048 * 3 * 2048];
__device__ __nv_bfloat16 g_Bp[(size_t)3 * 2048 * NCAT];

// ---------------- helpers ----------------
__device__ __forceinline__ float sigmoidf_(float x) { return 1.0f / (1.0f + expf(-x)); }

__device__ __forceinline__ float blockReduceSum128(float v, float* red) {
#pragma unroll
    for (int m = 16; m > 0; m >>= 1) v += __shfl_xor_sync(0xffffffffu, v, m);
    __syncthreads();
    if ((threadIdx.x & 31) == 0) red[threadIdx.x >> 5] = v;
    __syncthreads();
    return red[0] + red[1] + red[2] + red[3];
}

__device__ __forceinline__ void blockReduceSum3(float& a, float& b, float& c,
                                                float (*red)[3]) {
#pragma unroll
    for (int m = 16; m > 0; m >>= 1) {
        a += __shfl_xor_sync(0xffffffffu, a, m);
        b += __shfl_xor_sync(0xffffffffu, b, m);
        c += __shfl_xor_sync(0xffffffffu, c, m);
    }
    __syncthreads();
    if ((threadIdx.x & 31) == 0) {
        int w = threadIdx.x >> 5;
        red[w][0] = a;
        red[w][1] = b;
        red[w][2] = c;
    }
    __syncthreads();
    a = red[0][0] + red[1][0] + red[2][0] + red[3][0];
    b = red[0][1] + red[1][1] + red[2][1] + red[3][1];
    c = red[0][2] + red[1][2] + red[2][2] + red[3][2];
}

// packed f32x2 ops (sm_103a)
typedef unsigned long long ull;
__device__ __forceinline__ ull pack2(float x, float y) {
    ull r;
    asm("mov.b64 %0, {%1, %2};" : "=l"(r) : "f"(x), "f"(y));
    return r;
}
__device__ __forceinline__ float2 unpack2(ull v) {
    float x, y;
    asm("mov.b64 {%0, %1}, %2;" : "=f"(x), "=f"(y) : "l"(v));
    return make_float2(x, y);
}
__device__ __forceinline__ ull fma2_(ull a, ull b, ull c) {
    ull d;
    asm("fma.rn.f32x2 %0, %1, %2, %3;" : "=l"(d) : "l"(a), "l"(b), "l"(c));
    return d;
}
__device__ __forceinline__ ull mul2_(ull a, ull b) {
    ull d;
    asm("mul.rn.f32x2 %0, %1, %2;" : "=l"(d) : "l"(a), "l"(b));
    return d;
}

__device__ __forceinline__ uint32_t packsplit_hi(float a, float b) {
    __nv_bfloat162 h = __floats2bfloat162_rn(a, b);
    return *(uint32_t*)&h;
}
__device__ __forceinline__ uint32_t packsplit_lo(float a, float b, uint32_t hipack) {
    __nv_bfloat162* hp = (__nv_bfloat162*)&hipack;
    float ra = a - __bfloat162float(hp->x);
    float rb = b - __bfloat162float(hp->y);
    __nv_bfloat162 l = __floats2bfloat162_rn(ra, rb);
    return *(uint32_t*)&l;
}

// ---------------- split conversions (R8 K-tripled layouts) ----------------
__global__ void splitAmask_kernel(const float* __restrict__ x, const float* __restrict__ mask,
                                  __nv_bfloat16* __restrict__ Ap, int n2) {
    int i = blockIdx.x * blockDim.x + threadIdx.x;
    if (i >= n2) return;
    int i2 = i * 2;
    int r = i2 >> 11, c = i2 & 2047;
    float2 xv = *(const float2*)&x[i2];
    float m = mask[r];
    float v0 = xv.x * m, v1 = xv.y * m;
    uint32_t hi = packsplit_hi(v0, v1);
    uint32_t lo = packsplit_lo(v0, v1, hi);
    size_t base = (size_t)r * 6144 + c;
    *(uint32_t*)&Ap[base] = hi;
    *(uint32_t*)&Ap[base + 2048] = lo;
    *(uint32_t*)&Ap[base + 4096] = hi;
}

__global__ void splitBcat_kernel(const float* __restrict__ W_r, const float* __restrict__ W_k,
                                 const float* __restrict__ W_v, const float* __restrict__ w1,
                                 const float* __restrict__ a1, const float* __restrict__ v1,
                                 const float* __restrict__ k1, const float* __restrict__ g1,
                                 __nv_bfloat16* __restrict__ Bp, int n2) {
    int i = blockIdx.x * blockDim.x + threadIdx.x;
    if (i >= n2) return;
    int i2 = i * 2;
    int r = i2 / NCAT, c = i2 - r * NCAT;
    const float* src;
    int off, ncols;
    if (c < 2048) { src = W_r; off = OFF_XR; ncols = 2048; }
    else if (c < 2560) { src = W_k; off = OFF_XK; ncols = 512; }
    else if (c < 3072) { src = W_v; off = OFF_XV; ncols = 512; }
    else if (c < 3232) { src = w1; off = OFF_TW; ncols = 160; }
    else if (c < 3328) { src = a1; off = OFF_TA; ncols = 96; }
    else if (c < 3392) { src = v1; off = OFF_TV; ncols = 64; }
    else if (c < 3456) { src = k1; off = OFF_TK; ncols = 64; }
    else { src = g1; off = OFF_TG; ncols = 160; }
    float2 xv = *(const float2*)&src[(size_t)r * ncols + (c - off)];
    uint32_t hi = packsplit_hi(xv.x, xv.y);
    uint32_t lo = packsplit_lo(xv.x, xv.y, hi);
    size_t base = (size_t)r * NCAT + c;
    *(uint32_t*)&Bp[base] = hi;
    *(uint32_t*)&Bp[base + (size_t)2048 * NCAT] = hi;
    *(uint32_t*)&Bp[base + (size_t)4096 * NCAT] = lo;
}

__global__ void splitB_kernel(const float* __restrict__ B, __nv_bfloat16* __restrict__ Bp,
                              int K, int Ncols, int ldB, int colOff, int n2) {
    int i = blockIdx.x * blockDim.x + threadIdx.x;
    if (i >= n2) return;
    int i2 = i * 2;
    int r = i2 / Ncols, c = i2 - r * Ncols;
    float2 xv = *(const float2*)&B[i2];
    uint32_t hi = packsplit_hi(xv.x, xv.y);
    uint32_t lo = packsplit_lo(xv.x, xv.y, hi);
    size_t base = (size_t)r * ldB + colOff + c;
    *(uint32_t*)&Bp[base] = hi;
    *(uint32_t*)&Bp[base + (size_t)K * ldB] = hi;
    *(uint32_t*)&Bp[base + (size_t)2 * K * ldB] = lo;
}

__global__ void splitB2_kernel(const float* __restrict__ w2, const float* __restrict__ a2,
                               const float* __restrict__ g2, const float* __restrict__ v2,
                               const float* __restrict__ k2, __nv_bfloat16* __restrict__ Bp,
                               int n2) {
    int i = blockIdx.x * blockDim.x + threadIdx.x;
    if (i >= n2) return;
    int i2 = i * 2;
    const float* src;
    int K, N, local;
    size_t base;
    if (i2 < 327680) { src = w2; K = 160; N = 2048; base = BW_BASE; local = i2; }
    else if (i2 < 524288) { src = a2; K = 96; N = 2048; base = BA_BASE; local = i2 - 327680; }
    else if (i2 < 851968) { src = g2; K = 160; N = 2048; base = BG_BASE; local = i2 - 524288; }
    else if (i2 < 884736) { src = v2; K = 64; N = 512; base = BV_BASE; local = i2 - 851968; }
    else { src = k2; K = 64; N = 512; base = BK_BASE; local = i2 - 884736; }
    float2 xv = *(const float2*)&src[local];
    uint32_t hi = packsplit_hi(xv.x, xv.y);
    uint32_t lo = packsplit_lo(xv.x, xv.y, hi);
    size_t off = base + (size_t)local;
    *(uint32_t*)&Bp[off] = hi;
    *(uint32_t*)&Bp[off + (size_t)K * N] = hi;
    *(uint32_t*)&Bp[off + (size_t)2 * K * N] = lo;
}

// ---------------- fused act + stage-2 A-split from Ccat ----------------
__global__ void splitMids_kernel(const float* __restrict__ Ccat, __nv_bfloat16* __restrict__ Ap,
                                 int n2) {
    int i = blockIdx.x * blockDim.x + threadIdx.x;
    if (i >= n2) return;
    int i2 = i * 2;
    int t = i2 / NMID, c = i2 - t * NMID;
    const float* src = &Ccat[(size_t)t * NCAT + OFF_TW];
    float v0 = src[c], v1 = src[c + 1];
    int K, lc;
    size_t base;
    if (c < 160) {
        v0 = tanhf(v0); v1 = tanhf(v1);
        K = 160; base = APW_BASE; lc = c;
    } else if (c < 256) {
        K = 96; base = APA_BASE; lc = c - 160;
    } else if (c < 320) {
        K = 64; base = APV_BASE; lc = c - 256;
    } else if (c < 384) {
        K = 64; base = APK_BASE; lc = c - 320;
    } else {
        v0 = sigmoidf_(v0); v1 = sigmoidf_(v1);
        K = 160; base = APG_BASE; lc = c - 384;
    }
    uint32_t hi = packsplit_hi(v0, v1);
    uint32_t lo = packsplit_lo(v0, v1, hi);
    size_t off = base + (size_t)t * (3 * K) + lc;
    *(uint32_t*)&Ap[off] = hi;
    *(uint32_t*)&Ap[off + K] = lo;
    *(uint32_t*)&Ap[off + 2 * K] = hi;
}

// ---------------- fused merge + final A-split ----------------
__global__ void mergeSplitA_kernel(const float* __restrict__ y, const float* __restrict__ coef,
                                   const float* __restrict__ vf, const float* __restrict__ gbuf,
                                   __nv_bfloat16* __restrict__ Ap, int n2) {
    int i = blockIdx.x * blockDim.x + threadIdx.x;
    if (i >= n2) return;
    int i2 = i * 2;
    int t = i2 >> 11, hn = i2 & 2047;
    int h = hn >> 7, nn = hn & 127;
    float cf = coef[t * H_NUM + h];
    const float* vp = &vf[t * KVN_DIM + (h >> 2) * 128 + nn];
    float2 yv = *(const float2*)&y[i2];
    float2 gv = *(const float2*)&gbuf[i2];
    float v0 = (yv.x + cf * vp[0]) * gv.x;
    float v1 = (yv.y + cf * vp[1]) * gv.y;
    uint32_t hi = packsplit_hi(v0, v1);
    uint32_t lo = packsplit_lo(v0, v1, hi);
    size_t base = (size_t)t * 6144 + hn;
    *(uint32_t*)&Ap[base] = hi;
    *(uint32_t*)&Ap[base + 2048] = lo;
    *(uint32_t*)&Ap[base + 4096] = hi;
}

// ---------------- bf16 tensor-core GEMM, 3-stage cp.async pipeline (R8) ----------------
#define LDA_S 40
#define LDB_S 136
#define NSTAGE 3

__global__ __launch_bounds__(256) void bf16_gemm_kernel(
    const __nv_bfloat16* __restrict__ A, const __nv_bfloat16* __restrict__ B,
    float* __restrict__ C, int M, int N, int K3, int ldB, int ldC) {
    __shared__ __align__(16) __nv_bfloat16 As[NSTAGE][128 * LDA_S];
    __shared__ __align__(16) __nv_bfloat16 Bs[NSTAGE][32 * LDB_S];

    const int tid = threadIdx.x;
    const int bm = blockIdx.y * 128;
    const int bn = blockIdx.x * 128;
    const int warp = tid >> 5;
    const int lane = tid & 31;
    const int wm = warp & 3;
    const int wn = warp >> 2;

    const int ar = tid >> 2;
    const int ac = (tid & 3) * 8;
    const int br = tid >> 4;
    const int bc = (tid & 15) * 8;
    const int bsz = ((bn + bc) < N) ? 16 : 0;

    float c[2][8][4];
#pragma unroll
    for (int mi = 0; mi < 2; mi++)
#pragma unroll
        for (int ni = 0; ni < 8; ni++)
#pragma unroll
            for (int q = 0; q < 4; q++) c[mi][ni][q] = 0.0f;

    const int KT = K3 >> 5;

    auto load_stage = [&](int st, int kt) {
        int k0 = kt * 32;
#pragma unroll
        for (int it = 0; it < 2; it++) {
            const __nv_bfloat16* src = A + (size_t)(bm + ar + it * 64) * K3 + k0 + ac;
            uint32_t dst = (uint32_t)__cvta_generic_to_shared(&As[st][(ar + it * 64) * LDA_S + ac]);
            asm volatile("cp.async.ca.shared.global [%0], [%1], 16;\n" ::"r"(dst), "l"(src));
        }
#pragma unroll
        for (int it = 0; it < 2; it++) {
            const __nv_bfloat16* src = B + (size_t)(k0 + br + it * 16) * ldB + bn + bc;
            uint32_t dst = (uint32_t)__cvta_generic_to_shared(&Bs[st][(br + it * 16) * LDB_S + bc]);
            asm volatile("cp.async.ca.shared.global [%0], [%1], 16, %2;\n" ::"r"(dst), "l"(src),
                         "r"(bsz));
        }
        asm volatile("cp.async.commit_group;\n");
    };

    auto compute_stage = [&](int st) {
#pragma unroll
        for (int kk = 0; kk < 32; kk += 16) {
            uint32_t af[2][4];
#pragma unroll
            for (int mi = 0; mi < 2; mi++) {
                uint32_t addr = (uint32_t)__cvta_generic_to_shared(
                    &As[st][(wm * 32 + mi * 16 + (lane & 15)) * LDA_S + kk + (lane >> 4) * 8]);
                asm volatile("ldmatrix.sync.aligned.m8n8.x4.shared.b16 {%0,%1,%2,%3}, [%4];\n"
                             : "=r"(af[mi][0]), "=r"(af[mi][1]), "=r"(af[mi][2]), "=r"(af[mi][3])
                             : "r"(addr));
            }
            uint32_t bfr[8][2];
#pragma unroll
            for (int p = 0; p < 4; p++) {
                uint32_t addr = (uint32_t)__cvta_generic_to_shared(
                    &Bs[st][(kk + (lane & 15)) * LDB_S + wn * 64 + p * 16 + (lane >> 4) * 8]);
                uint32_t b0, b1, b2, b3;
                asm volatile("ldmatrix.sync.aligned.m8n8.x4.trans.shared.b16 {%0,%1,%2,%3}, [%4];\n"
                             : "=r"(b0), "=r"(b1), "=r"(b2), "=r"(b3)
                             : "r"(addr));
                bfr[p * 2][0] = b0;
                bfr[p * 2][1] = b1;
                bfr[p * 2 + 1][0] = b2;
                bfr[p * 2 + 1][1] = b3;
            }
#pragma unroll
            for (int mi = 0; mi < 2; mi++)
#pragma unroll
                for (int ni = 0; ni < 8; ni++) {
                    asm volatile(
                        "mma.sync.aligned.m16n8k16.row.col.f32.bf16.bf16.f32 "
                        "{%0,%1,%2,%3}, {%4,%5,%6,%7}, {%8,%9}, {%0,%1,%2,%3};\n"
                        : "+f"(c[mi][ni][0]), "+f"(c[mi][ni][1]), "+f"(c[mi][ni][2]),
                          "+f"(c[mi][ni][3])
                        : "r"(af[mi][0]), "r"(af[mi][1]), "r"(af[mi][2]), "r"(af[mi][3]),
                          "r"(bfr[ni][0]), "r"(bfr[ni][1]));
                }
        }
    };

    load_stage(0, 0);
    if (KT > 1) load_stage(1, 1);
    for (int kt = 0; kt < KT; kt++) {
        if (kt + 2 < KT) {
            load_stage((kt + 2) % NSTAGE, kt + 2);
            asm volatile("cp.async.wait_group 2;\n");
        } else if (kt + 1 < KT) {
            asm volatile("cp.async.wait_group 1;\n");
        } else {
            asm volatile("cp.async.wait_group 0;\n");
        }
        __syncthreads();
        compute_stage(kt % NSTAGE);
        __syncthreads();
    }

#pragma unroll
    for (int mi = 0; mi < 2; mi++) {
        int row = bm + wm * 32 + mi * 16 + (lane >> 2);
#pragma unroll
        for (int ni = 0; ni < 8; ni++) {
            int col = bn + wn * 64 + ni * 8 + (lane & 3) * 2;
            if (col < N) {
                C[(size_t)row * ldC + col] = c[mi][ni][0];
                C[(size_t)row * ldC + col + 1] = c[mi][ni][1];
                C[(size_t)(row + 8) * ldC + col] = c[mi][ni][2];
                C[(size_t)(row + 8) * ldC + col + 1] = c[mi][ni][3];
            }
        }
    }
}

// ---------------- postprocess per (t, kvh) ----------------
__global__ void pp_kv_kernel(const float* __restrict__ Ccat,
                             const float* __restrict__ kmix, const float* __restrict__ vmix,
                             const float* __restrict__ k_first, const float* __restrict__ v_first,
                             const float* __restrict__ k0, const float* __restrict__ v0,
                             const float* __restrict__ knw, const float* __restrict__ cosb,
                             const float* __restrict__ sinb,
                             float* __restrict__ kf, float* __restrict__ vfout,
                             float* __restrict__ kkout) {
    int t = blockIdx.x, kvh = blockIdx.y, n = threadIdx.x;
    int idx = t * KVN_DIM + kvh * 128 + n;
    size_t cidx = (size_t)t * NCAT + kvh * 128 + n;
    __shared__ float shk[128];
    __shared__ float red[4];

    float k = Ccat[cidx + OFF_XK];
    float ss = blockReduceSum128(k * k, red);
    float kn = knw[n] * k * rsqrtf(ss * (1.0f / 128.0f) + 1e-6f);
    shk[n] = kn;
    __syncthreads();
    float rh = (n < 64) ? -shk[n + 64] : shk[n - 64];
    float c = cosb[t * 128 + n], s = sinb[t * 128 + n];
    float kr = fmaf(kn, c, rh * s);

    float kfv = kr + (k_first[idx] - kr) * sigmoidf_(k0[kvh * 128 + n] + kmix[idx]);
    float vv = Ccat[cidx + OFF_XV];
    float vfv = vv + (v_first[idx] - vv) * sigmoidf_(v0[kvh * 128 + n] + vmix[idx]);

    float nrm2 = blockReduceSum128(kfv * kfv, red);
    float denom = fmaxf(sqrtf(nrm2), 1e-12f);

    kf[idx] = kfv;
    vfout[idx] = vfv;
    kkout[idx] = kfv / denom;
}

// ---------------- postprocess per (t, h) ----------------
__global__ void pp_h_kernel(const float* __restrict__ Ccat, const float* __restrict__ wfull,
                            const float* __restrict__ afull,
                            const float* __restrict__ w0, const float* __restrict__ a0,
                            const float* __restrict__ kkbuf, const float* __restrict__ kfbuf,
                            const float* __restrict__ rnw, const float* __restrict__ cosb,
                            const float* __restrict__ sinb, const float* __restrict__ r_k,
                            float* __restrict__ rout, float* __restrict__ wdout,
                            float* __restrict__ bbout, float* __restrict__ coef,
                            float2* __restrict__ c12) {
    int t = blockIdx.x, h = blockIdx.y, n = threadIdx.x;
    int hn = h * 128 + n;
    int idx = t * HN_DIM + hn;
    __shared__ float shr[128];
    __shared__ float red[4];
    __shared__ float red3[4][3];

    float r = Ccat[(size_t)t * NCAT + OFF_XR + hn];
    float ss = blockReduceSum128(r * r, red);
    float rn = rnw[n] * r * rsqrtf(ss * (1.0f / 128.0f) + 1e-6f);
    shr[n] = rn;
    __syncthreads();
    float rh = (n < 64) ? -shr[n + 64] : shr[n - 64];
    float c = cosb[t * 128 + n], s = sinb[t * 128 + n];
    float rr = fmaf(rn, c, rh * s);
    rout[idx] = rr;

    float z = w0[hn] + wfull[idx];
    float u = -z;
    float sp = fmaxf(u, 0.0f) + log1pf(expf(-fabsf(u)));
    float w = -sp - 0.5f;
    wdout[idx] = expf(-expf(w));

    float a = sigmoidf_(a0[hn] + afull[idx]);
    int kvidx = t * KVN_DIM + (h >> 2) * 128 + n;
    float kfv = kfbuf[kvidx];
    float bbv = kkbuf[kvidx] * a;
    bbout[idx] = bbv;

    float p0 = rr * kfv * r_k[hn];
    float p1 = bbv * rr;
    float p2 = kfv * rr;
    blockReduceSum3(p0, p1, p2, red3);
    if (n == 0) {
        coef[t * H_NUM + h] = p0;
        c12[t * H_NUM + h] = make_float2(p1, p2);
    }
}

// ---------------- sequential scan (R8: warp-autonomous + depth-4 prefetch) ----------------
__global__ __launch_bounds__(32) void scan_kernel(const float* __restrict__ wdec,
                                                  const float* __restrict__ bb,
                                                  const float* __restrict__ kk,
                                                  const float* __restrict__ kf,
                                                  const float* __restrict__ rr,
                                                  const float* __restrict__ vf,
                                                  const float2* __restrict__ c12,
                                                  float* __restrict__ y) {
    const int h = blockIdx.x;
    const int rg = blockIdx.y;
    const int lane = threadIdx.x;
    const int kvh = h >> 2;

    const int hoff = h * 128 + lane * 4;
    const int koff = kvh * 128 + lane * 4;
    const int voff = kvh * 128 + rg * 4;
    float* py = y + h * 128 + rg * 4;

    ull S2[4][2];
#pragma unroll
    for (int i = 0; i < 4; i++) { S2[i][0] = 0ull; S2[i][1] = 0ull; }

    float4 Pw[4], Pb[4], Pr[4], Pk[4], Pf[4], Pv[4];
    float2 Pc[4];
#pragma unroll
    for (int d = 0; d < 4; d++) {
        size_t oH = (size_t)d * HN_DIM;
        size_t oKV = (size_t)d * KVN_DIM;
        Pw[d] = *(const float4*)&wdec[oH + hoff];
        Pb[d] = *(const float4*)&bb[oH + hoff];
        Pr[d] = *(const float4*)&rr[oH + hoff];
        Pk[d] = *(const float4*)&kk[oKV + koff];
        Pf[d] = *(const float4*)&kf[oKV + koff];
        Pv[d] = *(const float4*)&vf[oKV + voff];
        Pc[d] = c12[d * H_NUM + h];
    }

    for (int t = 0; t < T_LEN; t += 4) {
#pragma unroll
        for (int u = 0; u < 4; u++) {
            float4 w4 = Pw[u], b4 = Pb[u], r4 = Pr[u], k4 = Pk[u], f4 = Pf[u], v4 = Pv[u];
            float2 cc = Pc[u];

            int tn = t + u + 4;
            if (tn > T_LEN - 1) tn = T_LEN - 1;
            size_t oH = (size_t)tn * HN_DIM;
            size_t oKV = (size_t)tn * KVN_DIM;
            Pw[u] = *(const float4*)&wdec[oH + hoff];
            Pb[u] = *(const float4*)&bb[oH + hoff];
            Pr[u] = *(const float4*)&rr[oH + hoff];
            Pk[u] = *(const float4*)&kk[oKV + koff];
            Pf[u] = *(const float4*)&kf[oKV + koff];
            Pv[u] = *(const float4*)&vf[oKV + voff];
            Pc[u] = c12[tn * H_NUM + h];

            ull wA = pack2(w4.x, w4.y), wB = pack2(w4.z, w4.w);
            ull bA = pack2(b4.x, b4.y), bB = pack2(b4.z, b4.w);
            ull kA = pack2(k4.x, k4.y), kB = pack2(k4.z, k4.w);
            ull fA = pack2(f4.x, f4.y), fB = pack2(f4.z, f4.w);
            ull wrA = pack2(w4.x * r4.x, w4.y * r4.y);
            ull wrB = pack2(w4.z * r4.z, w4.w * r4.w);

            float sa[4], d1[4];
#pragma unroll
            for (int i = 0; i < 4; i++) {
                ull sdp = fma2_(S2[i][1], kB, mul2_(S2[i][0], kA));
                float2 su = unpack2(sdp);
                sa[i] = su.x + su.y;
                ull ddp = fma2_(S2[i][1], wrB, mul2_(S2[i][0], wrA));
                float2 du = unpack2(ddp);
                d1[i] = du.x + du.y;
            }

#pragma unroll
            for (int m = 16; m > 0; m >>= 1) {
                sa[0] += __shfl_xor_sync(0xffffffffu, sa[0], m);
                sa[1] += __shfl_xor_sync(0xffffffffu, sa[1], m);
                sa[2] += __shfl_xor_sync(0xffffffffu, sa[2], m);
                sa[3] += __shfl_xor_sync(0xffffffffu, sa[3], m);
                d1[0] += __shfl_xor_sync(0xffffffffu, d1[0], m);
                d1[1] += __shfl_xor_sync(0xffffffffu, d1[1], m);
                d1[2] += __shfl_xor_sync(0xffffffffu, d1[2], m);
                d1[3] += __shfl_xor_sync(0xffffffffu, d1[3], m);
            }
#pragma unroll
            for (int i = 0; i < 4; i++) sa[i] = -sa[i];

            if (lane == 0) {
                float4 yo;
                yo.x = fmaf(sa[0], cc.x, fmaf(v4.x, cc.y, d1[0]));
                yo.y = fmaf(sa[1], cc.x, fmaf(v4.y, cc.y, d1[1]));
                yo.z = fmaf(sa[2], cc.x, fmaf(v4.z, cc.y, d1[2]));
                yo.w = fmaf(sa[3], cc.x, fmaf(v4.w, cc.y, d1[3]));
                *(float4*)&py[(size_t)(t + u) * HN_DIM] = yo;
            }

            const float vv[4] = {v4.x, v4.y, v4.z, v4.w};
#pragma unroll
            for (int i = 0; i < 4; i++) {
                ull sai = pack2(sa[i], sa[i]);
                ull vvi = pack2(vv[i], vv[i]);
                S2[i][0] = fma2_(S2[i][0], wA, fma2_(sai, bA, mul2_(vvi, fA)));
                S2[i][1] = fma2_(S2[i][1], wB, fma2_(sai, bB, mul2_(vvi, fB)));
            }
        }
    }
}

// ---------------- launch ----------------
static float* symAddrF(const void* sym) {
    void* p = nullptr;
    cudaGetSymbolAddress(&p, sym);
    return (float*)p;
}
static float2* symAddrF2(const void* sym) {
    void* p = nullptr;
    cudaGetSymbolAddress(&p, sym);
    return (float2*)p;
}
static __nv_bfloat16* symAddrB(const void* sym) {
    void* p = nullptr;
    cudaGetSymbolAddress(&p, sym);
    return (__nv_bfloat16*)p;
}

extern "C" void kernel_launch(void* const* d_in, const int* in_sizes, int n_in,
                              void* d_out, int out_size) {
    const float* x = (const float*)d_in[0];
    const float* v_first = (const float*)d_in[1];
    const float* k_first = (const float*)d_in[2];
    const float* amask = (const float*)d_in[3];
    const float* cosb = (const float*)d_in[4];
    const float* sinb = (const float*)d_in[5];
    const float* w0 = (const float*)d_in[6];
    const float* w1 = (const float*)d_in[7];
    const float* w2 = (const float*)d_in[8];
    const float* a0 = (const float*)d_in[9];
    const float* a1 = (const float*)d_in[10];
    const float* a2 = (const float*)d_in[11];
    const float* v0 = (const float*)d_in[12];
    const float* v1 = (const float*)d_in[13];
    const float* v2 = (const float*)d_in[14];
    const float* k0 = (const float*)d_in[15];
    const float* k1 = (const float*)d_in[16];
    const float* k2 = (const float*)d_in[17];
    const float* g1 = (const float*)d_in[18];
    const float* g2 = (const float*)d_in[19];
    const float* r_k = (const float*)d_in[20];
    const float* r_norm_w = (const float*)d_in[21];
    const float* k_norm_w = (const float*)d_in[22];
    const float* W_r = (const float*)d_in[23];
    const float* W_k = (const float*)d_in[24];
    const float* W_v = (const float*)d_in[25];
    const float* W_o = (const float*)d_in[26];
    float* out = (float*)d_out;

    float* Ccat = symAddrF(g_Ccat);
    float* wfull = symAddrF(g_wfull);
    float* afull = symAddrF(g_afull);
    float* gfull = symAddrF(g_gfull);
    float* vmix = symAddrF(g_vmix);
    float* kmix = symAddrF(g_kmix);
    float* rrb = symAddrF(g_rr);
    float* kf = symAddrF(g_kf);
    float* vf = symAddrF(g_vf);
    float* kkb = symAddrF(g_kk);
    float* wd = symAddrF(g_wd);
    float* bbb = symAddrF(g_bb);
    float* coef = symAddrF(g_coef);
    float2* c12 = symAddrF2(g_c12);
    float* yb = symAddrF(g_y);
    __nv_bfloat16* Ap = symAddrB(g_Ap);
    __nv_bfloat16* Bp = symAddrB(g_Bp);

    // one-time side stream + events (created on first, non-captured call)
    static cudaStream_t sideStream = nullptr;
    static cudaEvent_t evFork = nullptr, evJoin = nullptr;
    if (sideStream == nullptr) {
        cudaStreamCreateWithFlags(&sideStream, cudaStreamNonBlocking);
        cudaEventCreateWithFlags(&evFork, cudaEventDisableTiming);
        cudaEventCreateWithFlags(&evJoin, cudaEventDisableTiming);
    }

    // ---- stage 1 (main stream) ----
    const int NTC2 = T_LEN * C_DIM / 2;
    splitAmask_kernel<<<(NTC2 + 255) / 256, 256>>>(x, amask, Ap, NTC2);

    const int NB2 = T_LEN * NCAT / 2;
    splitBcat_kernel<<<(NB2 + 255) / 256, 256>>>(W_r, W_k, W_v, w1, a1, v1, k1, g1, Bp, NB2);

    {
        dim3 grid((NCAT + 127) / 128, 2048 / 128);
        bf16_gemm_kernel<<<grid, 256>>>(Ap, Bp, Ccat, 2048, NCAT, 6144, NCAT, NCAT);
    }

    // ---- fused activations + stage-2 A splits ----
    const int NMIDS2 = T_LEN * NMID / 2;
    splitMids_kernel<<<(NMIDS2 + 255) / 256, 256>>>(Ccat, Ap, NMIDS2);

    // ---- stage-2 B splits ----
    {
        const int n2 = 917504 / 2;
        splitB2_kernel<<<(n2 + 255) / 256, 256>>>(w2, a2, g2, v2, k2, Bp, n2);
    }

    // ---- FORK: side stream does g-path GEMM + W_o split (hidden under main work/scan) ----
    cudaEventRecord(evFork, 0);
    cudaStreamWaitEvent(sideStream, evFork, 0);
    {
        dim3 grid(2048 / 128, 2048 / 128);
        bf16_gemm_kernel<<<grid, 256, 0, sideStream>>>(Ap + APG_BASE, Bp + BG_BASE, gfull,
                                                       2048, 2048, 480, 2048, 2048);
        int n2 = 2048 * 2048 / 2;
        splitB_kernel<<<(n2 + 255) / 256, 256, 0, sideStream>>>(W_o, Bp + BWO_BASE, 2048, 2048,
                                                                2048, 0, n2);
    }
    cudaEventRecord(evJoin, sideStream);

    // ---- main stream: remaining stage-2 GEMMs ----
    auto gemm2 = [&](size_t aBase, size_t bBase, int K, float* C, int N) {
        dim3 grid((N + 127) / 128, 2048 / 128);
        bf16_gemm_kernel<<<grid, 256>>>(Ap + aBase, Bp + bBase, C, 2048, N, 3 * K, N, N);
    };
    gemm2(APW_BASE, BW_BASE, 160, wfull, 2048);
    gemm2(APA_BASE, BA_BASE, 96, afull, 2048);
    gemm2(APV_BASE, BV_BASE, 64, vmix, 512);
    gemm2(APK_BASE, BK_BASE, 64, kmix, 512);

    // ---- postprocess (R8 kernels) ----
    pp_kv_kernel<<<dim3(T_LEN, KVH_NUM), 128>>>(Ccat, kmix, vmix, k_first, v_first,
                                                k0, v0, k_norm_w, cosb, sinb,
                                                kf, vf, kkb);
    pp_h_kernel<<<dim3(T_LEN, H_NUM), 128>>>(Ccat, wfull, afull, w0, a0, kkb, kf,
                                             r_norm_w, cosb, sinb, r_k,
                                             rrb, wd, bbb, coef, c12);

    // ---- sequential scan (side-stream work overlaps with this) ----
    scan_kernel<<<dim3(H_NUM, 32), 32>>>(wd, bbb, kkb, kf, rrb, vf, c12, yb);

    // ---- JOIN before consuming gfull / writing Ap ----
    cudaStreamWaitEvent(0, evJoin, 0);

    // ---- fused merge + final A split ----
    const int NHN2 = T_LEN * HN_DIM / 2;
    mergeSplitA_kernel<<<(NHN2 + 255) / 256, 256>>>(yb, coef, vf, gfull, Ap, NHN2);

    // ---- final projection (W_o B' prepared on side stream) ----
    {
        dim3 grid(2048 / 128, 2048 / 128);
        bf16_gemm_kernel<<<grid, 256>>>(Ap, Bp + BWO_BASE, out, 2048, 2048, 6144, 2048, 2048);
    }
}

// round 16
// speedup vs baseline: 1.1838x; 1.0534x over previous
#include <cuda_runtime.h>
#include <cuda_bf16.h>
#include <cstdint>

#define T_LEN 2048
#define C_DIM 2048
#define H_NUM 16
#define N_DIM 128
#define KVH_NUM 4
#define HN_DIM 2048
#define KVN_DIM 512

// fused stage-1 output column offsets
#define OFF_XR 0
#define OFF_XK 2048
#define OFF_XV 2560
#define OFF_TW 3072
#define OFF_TA 3232
#define OFF_TV 3328
#define OFF_TK 3392
#define OFF_TG 3456
#define NCAT 3616
#define NMID 544

// stage-2 A' regions inside g_Ap (element offsets; K-tripled, row stride 3K)
#define APW_BASE 0
#define APA_BASE 983040
#define APG_BASE 1572864
#define APV_BASE 2555904
#define APK_BASE 2949120

// stage-2 B' regions inside g_Bp (element offsets; 3K rows x N)
#define BW_BASE 0
#define BA_BASE 983040
#define BG_BASE 1572864
#define BV_BASE 2555904
#define BK_BASE 2654208
// W_o B' region (private; avoids racing stage-2 reads when split runs on side stream)
#define BWO_BASE 4194304

// ---------------- scratch ----------------
__device__ float g_Ccat[(size_t)T_LEN * NCAT];
__device__ float g_wfull[T_LEN * HN_DIM];
__device__ float g_afull[T_LEN * HN_DIM];
__device__ float g_gfull[T_LEN * HN_DIM];
__device__ float g_vmix[T_LEN * KVN_DIM];
__device__ float g_kmix[T_LEN * KVN_DIM];
__device__ float g_rr[T_LEN * HN_DIM];
__device__ float g_kf[T_LEN * KVN_DIM];
__device__ float g_vf[T_LEN * KVN_DIM];
__device__ float g_kk[T_LEN * KVN_DIM];
__device__ float g_wd[T_LEN * HN_DIM];
__device__ float g_bb[T_LEN * HN_DIM];
__device__ float g_coef[T_LEN * H_NUM];
__device__ float2 g_c12[T_LEN * H_NUM];
__device__ float g_y[T_LEN * HN_DIM];

__device__ __nv_bfloat16 g_Ap[(size_t)2048 * 3 * 2048];
__device__ __nv_bfloat16 g_Bp[(size_t)3 * 2048 * NCAT];

// ---------------- helpers ----------------
__device__ __forceinline__ float sigmoidf_(float x) { return 1.0f / (1.0f + expf(-x)); }

__device__ __forceinline__ float blockReduceSum128(float v, float* red) {
#pragma unroll
    for (int m = 16; m > 0; m >>= 1) v += __shfl_xor_sync(0xffffffffu, v, m);
    __syncthreads();
    if ((threadIdx.x & 31) == 0) red[threadIdx.x >> 5] = v;
    __syncthreads();
    return red[0] + red[1] + red[2] + red[3];
}

__device__ __forceinline__ void blockReduceSum3(float& a, float& b, float& c,
                                                float (*red)[3]) {
#pragma unroll
    for (int m = 16; m > 0; m >>= 1) {
        a += __shfl_xor_sync(0xffffffffu, a, m);
        b += __shfl_xor_sync(0xffffffffu, b, m);
        c += __shfl_xor_sync(0xffffffffu, c, m);
    }
    __syncthreads();
    if ((threadIdx.x & 31) == 0) {
        int w = threadIdx.x >> 5;
        red[w][0] = a;
        red[w][1] = b;
        red[w][2] = c;
    }
    __syncthreads();
    a = red[0][0] + red[1][0] + red[2][0] + red[3][0];
    b = red[0][1] + red[1][1] + red[2][1] + red[3][1];
    c = red[0][2] + red[1][2] + red[2][2] + red[3][2];
}

// packed f32x2 ops (sm_103a)
typedef unsigned long long ull;
__device__ __forceinline__ ull pack2(float x, float y) {
    ull r;
    asm("mov.b64 %0, {%1, %2};" : "=l"(r) : "f"(x), "f"(y));
    return r;
}
__device__ __forceinline__ float2 unpack2(ull v) {
    float x, y;
    asm("mov.b64 {%0, %1}, %2;" : "=f"(x), "=f"(y) : "l"(v));
    return make_float2(x, y);
}
__device__ __forceinline__ ull fma2_(ull a, ull b, ull c) {
    ull d;
    asm("fma.rn.f32x2 %0, %1, %2, %3;" : "=l"(d) : "l"(a), "l"(b), "l"(c));
    return d;
}
__device__ __forceinline__ ull mul2_(ull a, ull b) {
    ull d;
    asm("mul.rn.f32x2 %0, %1, %2;" : "=l"(d) : "l"(a), "l"(b));
    return d;
}

__device__ __forceinline__ uint32_t packsplit_hi(float a, float b) {
    __nv_bfloat162 h = __floats2bfloat162_rn(a, b);
    return *(uint32_t*)&h;
}
__device__ __forceinline__ uint32_t packsplit_lo(float a, float b, uint32_t hipack) {
    __nv_bfloat162* hp = (__nv_bfloat162*)&hipack;
    float ra = a - __bfloat162float(hp->x);
    float rb = b - __bfloat162float(hp->y);
    __nv_bfloat162 l = __floats2bfloat162_rn(ra, rb);
    return *(uint32_t*)&l;
}

// ---------------- split conversions (R8 K-tripled layouts) ----------------
__global__ void splitAmask_kernel(const float* __restrict__ x, const float* __restrict__ mask,
                                  __nv_bfloat16* __restrict__ Ap, int n2) {
    int i = blockIdx.x * blockDim.x + threadIdx.x;
    if (i >= n2) return;
    int i2 = i * 2;
    int r = i2 >> 11, c = i2 & 2047;
    float2 xv = *(const float2*)&x[i2];
    float m = mask[r];
    float v0 = xv.x * m, v1 = xv.y * m;
    uint32_t hi = packsplit_hi(v0, v1);
    uint32_t lo = packsplit_lo(v0, v1, hi);
    size_t base = (size_t)r * 6144 + c;
    *(uint32_t*)&Ap[base] = hi;
    *(uint32_t*)&Ap[base + 2048] = lo;
    *(uint32_t*)&Ap[base + 4096] = hi;
}

__global__ void splitBcat_kernel(const float* __restrict__ W_r, const float* __restrict__ W_k,
                                 const float* __restrict__ W_v, const float* __restrict__ w1,
                                 const float* __restrict__ a1, const float* __restrict__ v1,
                                 const float* __restrict__ k1, const float* __restrict__ g1,
                                 __nv_bfloat16* __restrict__ Bp, int n2) {
    int i = blockIdx.x * blockDim.x + threadIdx.x;
    if (i >= n2) return;
    int i2 = i * 2;
    int r = i2 / NCAT, c = i2 - r * NCAT;
    const float* src;
    int off, ncols;
    if (c < 2048) { src = W_r; off = OFF_XR; ncols = 2048; }
    else if (c < 2560) { src = W_k; off = OFF_XK; ncols = 512; }
    else if (c < 3072) { src = W_v; off = OFF_XV; ncols = 512; }
    else if (c < 3232) { src = w1; off = OFF_TW; ncols = 160; }
    else if (c < 3328) { src = a1; off = OFF_TA; ncols = 96; }
    else if (c < 3392) { src = v1; off = OFF_TV; ncols = 64; }
    else if (c < 3456) { src = k1; off = OFF_TK; ncols = 64; }
    else { src = g1; off = OFF_TG; ncols = 160; }
    float2 xv = *(const float2*)&src[(size_t)r * ncols + (c - off)];
    uint32_t hi = packsplit_hi(xv.x, xv.y);
    uint32_t lo = packsplit_lo(xv.x, xv.y, hi);
    size_t base = (size_t)r * NCAT + c;
    *(uint32_t*)&Bp[base] = hi;
    *(uint32_t*)&Bp[base + (size_t)2048 * NCAT] = hi;
    *(uint32_t*)&Bp[base + (size_t)4096 * NCAT] = lo;
}

__global__ void splitB_kernel(const float* __restrict__ B, __nv_bfloat16* __restrict__ Bp,
                              int K, int Ncols, int ldB, int colOff, int n2) {
    int i = blockIdx.x * blockDim.x + threadIdx.x;
    if (i >= n2) return;
    int i2 = i * 2;
    int r = i2 / Ncols, c = i2 - r * Ncols;
    float2 xv = *(const float2*)&B[i2];
    uint32_t hi = packsplit_hi(xv.x, xv.y);
    uint32_t lo = packsplit_lo(xv.x, xv.y, hi);
    size_t base = (size_t)r * ldB + colOff + c;
    *(uint32_t*)&Bp[base] = hi;
    *(uint32_t*)&Bp[base + (size_t)K * ldB] = hi;
    *(uint32_t*)&Bp[base + (size_t)2 * K * ldB] = lo;
}

__global__ void splitB2_kernel(const float* __restrict__ w2, const float* __restrict__ a2,
                               const float* __restrict__ g2, const float* __restrict__ v2,
                               const float* __restrict__ k2, __nv_bfloat16* __restrict__ Bp,
                               int n2) {
    int i = blockIdx.x * blockDim.x + threadIdx.x;
    if (i >= n2) return;
    int i2 = i * 2;
    const float* src;
    int K, N, local;
    size_t base;
    if (i2 < 327680) { src = w2; K = 160; N = 2048; base = BW_BASE; local = i2; }
    else if (i2 < 524288) { src = a2; K = 96; N = 2048; base = BA_BASE; local = i2 - 327680; }
    else if (i2 < 851968) { src = g2; K = 160; N = 2048; base = BG_BASE; local = i2 - 524288; }
    else if (i2 < 884736) { src = v2; K = 64; N = 512; base = BV_BASE; local = i2 - 851968; }
    else { src = k2; K = 64; N = 512; base = BK_BASE; local = i2 - 884736; }
    float2 xv = *(const float2*)&src[local];
    uint32_t hi = packsplit_hi(xv.x, xv.y);
    uint32_t lo = packsplit_lo(xv.x, xv.y, hi);
    size_t off = base + (size_t)local;
    *(uint32_t*)&Bp[off] = hi;
    *(uint32_t*)&Bp[off + (size_t)K * N] = hi;
    *(uint32_t*)&Bp[off + (size_t)2 * K * N] = lo;
}

// ---------------- fused act + stage-2 A-split from Ccat ----------------
__global__ void splitMids_kernel(const float* __restrict__ Ccat, __nv_bfloat16* __restrict__ Ap,
                                 int n2) {
    int i = blockIdx.x * blockDim.x + threadIdx.x;
    if (i >= n2) return;
    int i2 = i * 2;
    int t = i2 / NMID, c = i2 - t * NMID;
    const float* src = &Ccat[(size_t)t * NCAT + OFF_TW];
    float v0 = src[c], v1 = src[c + 1];
    int K, lc;
    size_t base;
    if (c < 160) {
        v0 = tanhf(v0); v1 = tanhf(v1);
        K = 160; base = APW_BASE; lc = c;
    } else if (c < 256) {
        K = 96; base = APA_BASE; lc = c - 160;
    } else if (c < 320) {
        K = 64; base = APV_BASE; lc = c - 256;
    } else if (c < 384) {
        K = 64; base = APK_BASE; lc = c - 320;
    } else {
        v0 = sigmoidf_(v0); v1 = sigmoidf_(v1);
        K = 160; base = APG_BASE; lc = c - 384;
    }
    uint32_t hi = packsplit_hi(v0, v1);
    uint32_t lo = packsplit_lo(v0, v1, hi);
    size_t off = base + (size_t)t * (3 * K) + lc;
    *(uint32_t*)&Ap[off] = hi;
    *(uint32_t*)&Ap[off + K] = lo;
    *(uint32_t*)&Ap[off + 2 * K] = hi;
}

// ---------------- fused merge + final A-split ----------------
__global__ void mergeSplitA_kernel(const float* __restrict__ y, const float* __restrict__ coef,
                                   const float* __restrict__ vf, const float* __restrict__ gbuf,
                                   __nv_bfloat16* __restrict__ Ap, int n2) {
    int i = blockIdx.x * blockDim.x + threadIdx.x;
    if (i >= n2) return;
    int i2 = i * 2;
    int t = i2 >> 11, hn = i2 & 2047;
    int h = hn >> 7, nn = hn & 127;
    float cf = coef[t * H_NUM + h];
    const float* vp = &vf[t * KVN_DIM + (h >> 2) * 128 + nn];
    float2 yv = *(const float2*)&y[i2];
    float2 gv = *(const float2*)&gbuf[i2];
    float v0 = (yv.x + cf * vp[0]) * gv.x;
    float v1 = (yv.y + cf * vp[1]) * gv.y;
    uint32_t hi = packsplit_hi(v0, v1);
    uint32_t lo = packsplit_lo(v0, v1, hi);
    size_t base = (size_t)t * 6144 + hn;
    *(uint32_t*)&Ap[base] = hi;
    *(uint32_t*)&Ap[base + 2048] = lo;
    *(uint32_t*)&Ap[base + 4096] = hi;
}

// ---------------- bf16 tensor-core GEMM, 3-stage cp.async pipeline (R8) ----------------
#define LDA_S 40
#define LDB_S 136
#define NSTAGE 3

__global__ __launch_bounds__(256) void bf16_gemm_kernel(
    const __nv_bfloat16* __restrict__ A, const __nv_bfloat16* __restrict__ B,
    float* __restrict__ C, int M, int N, int K3, int ldB, int ldC) {
    __shared__ __align__(16) __nv_bfloat16 As[NSTAGE][128 * LDA_S];
    __shared__ __align__(16) __nv_bfloat16 Bs[NSTAGE][32 * LDB_S];

    const int tid = threadIdx.x;
    const int bm = blockIdx.y * 128;
    const int bn = blockIdx.x * 128;
    const int warp = tid >> 5;
    const int lane = tid & 31;
    const int wm = warp & 3;
    const int wn = warp >> 2;

    const int ar = tid >> 2;
    const int ac = (tid & 3) * 8;
    const int br = tid >> 4;
    const int bc = (tid & 15) * 8;
    const int bsz = ((bn + bc) < N) ? 16 : 0;

    float c[2][8][4];
#pragma unroll
    for (int mi = 0; mi < 2; mi++)
#pragma unroll
        for (int ni = 0; ni < 8; ni++)
#pragma unroll
            for (int q = 0; q < 4; q++) c[mi][ni][q] = 0.0f;

    const int KT = K3 >> 5;

    auto load_stage = [&](int st, int kt) {
        int k0 = kt * 32;
#pragma unroll
        for (int it = 0; it < 2; it++) {
            const __nv_bfloat16* src = A + (size_t)(bm + ar + it * 64) * K3 + k0 + ac;
            uint32_t dst = (uint32_t)__cvta_generic_to_shared(&As[st][(ar + it * 64) * LDA_S + ac]);
            asm volatile("cp.async.ca.shared.global [%0], [%1], 16;\n" ::"r"(dst), "l"(src));
        }
#pragma unroll
        for (int it = 0; it < 2; it++) {
            const __nv_bfloat16* src = B + (size_t)(k0 + br + it * 16) * ldB + bn + bc;
            uint32_t dst = (uint32_t)__cvta_generic_to_shared(&Bs[st][(br + it * 16) * LDB_S + bc]);
            asm volatile("cp.async.ca.shared.global [%0], [%1], 16, %2;\n" ::"r"(dst), "l"(src),
                         "r"(bsz));
        }
        asm volatile("cp.async.commit_group;\n");
    };

    auto compute_stage = [&](int st) {
#pragma unroll
        for (int kk = 0; kk < 32; kk += 16) {
            uint32_t af[2][4];
#pragma unroll
            for (int mi = 0; mi < 2; mi++) {
                uint32_t addr = (uint32_t)__cvta_generic_to_shared(
                    &As[st][(wm * 32 + mi * 16 + (lane & 15)) * LDA_S + kk + (lane >> 4) * 8]);
                asm volatile("ldmatrix.sync.aligned.m8n8.x4.shared.b16 {%0,%1,%2,%3}, [%4];\n"
                             : "=r"(af[mi][0]), "=r"(af[mi][1]), "=r"(af[mi][2]), "=r"(af[mi][3])
                             : "r"(addr));
            }
            uint32_t bfr[8][2];
#pragma unroll
            for (int p = 0; p < 4; p++) {
                uint32_t addr = (uint32_t)__cvta_generic_to_shared(
                    &Bs[st][(kk + (lane & 15)) * LDB_S + wn * 64 + p * 16 + (lane >> 4) * 8]);
                uint32_t b0, b1, b2, b3;
                asm volatile("ldmatrix.sync.aligned.m8n8.x4.trans.shared.b16 {%0,%1,%2,%3}, [%4];\n"
                             : "=r"(b0), "=r"(b1), "=r"(b2), "=r"(b3)
                             : "r"(addr));
                bfr[p * 2][0] = b0;
                bfr[p * 2][1] = b1;
                bfr[p * 2 + 1][0] = b2;
                bfr[p * 2 + 1][1] = b3;
            }
#pragma unroll
            for (int mi = 0; mi < 2; mi++)
#pragma unroll
                for (int ni = 0; ni < 8; ni++) {
                    asm volatile(
                        "mma.sync.aligned.m16n8k16.row.col.f32.bf16.bf16.f32 "
                        "{%0,%1,%2,%3}, {%4,%5,%6,%7}, {%8,%9}, {%0,%1,%2,%3};\n"
                        : "+f"(c[mi][ni][0]), "+f"(c[mi][ni][1]), "+f"(c[mi][ni][2]),
                          "+f"(c[mi][ni][3])
                        : "r"(af[mi][0]), "r"(af[mi][1]), "r"(af[mi][2]), "r"(af[mi][3]),
                          "r"(bfr[ni][0]), "r"(bfr[ni][1]));
                }
        }
    };

    load_stage(0, 0);
    if (KT > 1) load_stage(1, 1);
    for (int kt = 0; kt < KT; kt++) {
        if (kt + 2 < KT) {
            load_stage((kt + 2) % NSTAGE, kt + 2);
            asm volatile("cp.async.wait_group 2;\n");
        } else if (kt + 1 < KT) {
            asm volatile("cp.async.wait_group 1;\n");
        } else {
            asm volatile("cp.async.wait_group 0;\n");
        }
        __syncthreads();
        compute_stage(kt % NSTAGE);
        __syncthreads();
    }

#pragma unroll
    for (int mi = 0; mi < 2; mi++) {
        int row = bm + wm * 32 + mi * 16 + (lane >> 2);
#pragma unroll
        for (int ni = 0; ni < 8; ni++) {
            int col = bn + wn * 64 + ni * 8 + (lane & 3) * 2;
            if (col < N) {
                C[(size_t)row * ldC + col] = c[mi][ni][0];
                C[(size_t)row * ldC + col + 1] = c[mi][ni][1];
                C[(size_t)(row + 8) * ldC + col] = c[mi][ni][2];
                C[(size_t)(row + 8) * ldC + col + 1] = c[mi][ni][3];
            }
        }
    }
}

// ---------------- postprocess per (t, kvh) ----------------
__global__ void pp_kv_kernel(const float* __restrict__ Ccat,
                             const float* __restrict__ kmix, const float* __restrict__ vmix,
                             const float* __restrict__ k_first, const float* __restrict__ v_first,
                             const float* __restrict__ k0, const float* __restrict__ v0,
                             const float* __restrict__ knw, const float* __restrict__ cosb,
                             const float* __restrict__ sinb,
                             float* __restrict__ kf, float* __restrict__ vfout,
                             float* __restrict__ kkout) {
    int t = blockIdx.x, kvh = blockIdx.y, n = threadIdx.x;
    int idx = t * KVN_DIM + kvh * 128 + n;
    size_t cidx = (size_t)t * NCAT + kvh * 128 + n;
    __shared__ float shk[128];
    __shared__ float red[4];

    float k = Ccat[cidx + OFF_XK];
    float ss = blockReduceSum128(k * k, red);
    float kn = knw[n] * k * rsqrtf(ss * (1.0f / 128.0f) + 1e-6f);
    shk[n] = kn;
    __syncthreads();
    float rh = (n < 64) ? -shk[n + 64] : shk[n - 64];
    float c = cosb[t * 128 + n], s = sinb[t * 128 + n];
    float kr = fmaf(kn, c, rh * s);

    float kfv = kr + (k_first[idx] - kr) * sigmoidf_(k0[kvh * 128 + n] + kmix[idx]);
    float vv = Ccat[cidx + OFF_XV];
    float vfv = vv + (v_first[idx] - vv) * sigmoidf_(v0[kvh * 128 + n] + vmix[idx]);

    float nrm2 = blockReduceSum128(kfv * kfv, red);
    float denom = fmaxf(sqrtf(nrm2), 1e-12f);

    kf[idx] = kfv;
    vfout[idx] = vfv;
    kkout[idx] = kfv / denom;
}

// ---------------- postprocess per (t, h) ----------------
__global__ void pp_h_kernel(const float* __restrict__ Ccat, const float* __restrict__ wfull,
                            const float* __restrict__ afull,
                            const float* __restrict__ w0, const float* __restrict__ a0,
                            const float* __restrict__ kkbuf, const float* __restrict__ kfbuf,
                            const float* __restrict__ rnw, const float* __restrict__ cosb,
                            const float* __restrict__ sinb, const float* __restrict__ r_k,
                            float* __restrict__ rout, float* __restrict__ wdout,
                            float* __restrict__ bbout, float* __restrict__ coef,
                            float2* __restrict__ c12) {
    int t = blockIdx.x, h = blockIdx.y, n = threadIdx.x;
    int hn = h * 128 + n;
    int idx = t * HN_DIM + hn;
    __shared__ float shr[128];
    __shared__ float red[4];
    __shared__ float red3[4][3];

    float r = Ccat[(size_t)t * NCAT + OFF_XR + hn];
    float ss = blockReduceSum128(r * r, red);
    float rn = rnw[n] * r * rsqrtf(ss * (1.0f / 128.0f) + 1e-6f);
    shr[n] = rn;
    __syncthreads();
    float rh = (n < 64) ? -shr[n + 64] : shr[n - 64];
    float c = cosb[t * 128 + n], s = sinb[t * 128 + n];
    float rr = fmaf(rn, c, rh * s);
    rout[idx] = rr;

    float z = w0[hn] + wfull[idx];
    float u = -z;
    float sp = fmaxf(u, 0.0f) + log1pf(expf(-fabsf(u)));
    float w = -sp - 0.5f;
    wdout[idx] = expf(-expf(w));

    float a = sigmoidf_(a0[hn] + afull[idx]);
    int kvidx = t * KVN_DIM + (h >> 2) * 128 + n;
    float kfv = kfbuf[kvidx];
    float bbv = kkbuf[kvidx] * a;
    bbout[idx] = bbv;

    float p0 = rr * kfv * r_k[hn];
    float p1 = bbv * rr;
    float p2 = kfv * rr;
    blockReduceSum3(p0, p1, p2, red3);
    if (n == 0) {
        coef[t * H_NUM + h] = p0;
        c12[t * H_NUM + h] = make_float2(p1, p2);
    }
}

// ---------------- sequential scan (v8: warp-autonomous + depth-6 prefetch) ----------------
// grid (16 h, 32 rowgroups), 32 threads = 1 warp. 6-slot circular register pipeline:
// main loop strides 6 steps (341 iters = 2046 steps); slot u always holds step t+u.
// 2-step tail consumes slots 0,1. ~50% more DRAM-latency tolerance than depth-4.
__global__ __launch_bounds__(32) void scan_kernel(const float* __restrict__ wdec,
                                                  const float* __restrict__ bb,
                                                  const float* __restrict__ kk,
                                                  const float* __restrict__ kf,
                                                  const float* __restrict__ rr,
                                                  const float* __restrict__ vf,
                                                  const float2* __restrict__ c12,
                                                  float* __restrict__ y) {
    const int h = blockIdx.x;
    const int rg = blockIdx.y;
    const int lane = threadIdx.x;
    const int kvh = h >> 2;

    const int hoff = h * 128 + lane * 4;
    const int koff = kvh * 128 + lane * 4;
    const int voff = kvh * 128 + rg * 4;
    float* py = y + h * 128 + rg * 4;

    ull S2[4][2];
#pragma unroll
    for (int i = 0; i < 4; i++) { S2[i][0] = 0ull; S2[i][1] = 0ull; }

    float4 Pw[6], Pb[6], Pr[6], Pk[6], Pf[6], Pv[6];
    float2 Pc[6];
#pragma unroll
    for (int d = 0; d < 6; d++) {
        size_t oH = (size_t)d * HN_DIM;
        size_t oKV = (size_t)d * KVN_DIM;
        Pw[d] = *(const float4*)&wdec[oH + hoff];
        Pb[d] = *(const float4*)&bb[oH + hoff];
        Pr[d] = *(const float4*)&rr[oH + hoff];
        Pk[d] = *(const float4*)&kk[oKV + koff];
        Pf[d] = *(const float4*)&kf[oKV + koff];
        Pv[d] = *(const float4*)&vf[oKV + voff];
        Pc[d] = c12[d * H_NUM + h];
    }

    // one scan step consuming slot u (data = step tt); optionally refill slot u with step tn
    auto step = [&](int u, int tt, bool doRefill, int tn) {
        float4 w4 = Pw[u], b4 = Pb[u], r4 = Pr[u], k4 = Pk[u], f4 = Pf[u], v4 = Pv[u];
        float2 cc = Pc[u];

        if (doRefill) {
            size_t oH = (size_t)tn * HN_DIM;
            size_t oKV = (size_t)tn * KVN_DIM;
            Pw[u] = *(const float4*)&wdec[oH + hoff];
            Pb[u] = *(const float4*)&bb[oH + hoff];
            Pr[u] = *(const float4*)&rr[oH + hoff];
            Pk[u] = *(const float4*)&kk[oKV + koff];
            Pf[u] = *(const float4*)&kf[oKV + koff];
            Pv[u] = *(const float4*)&vf[oKV + voff];
            Pc[u] = c12[tn * H_NUM + h];
        }

        ull wA = pack2(w4.x, w4.y), wB = pack2(w4.z, w4.w);
        ull bA = pack2(b4.x, b4.y), bB = pack2(b4.z, b4.w);
        ull kA = pack2(k4.x, k4.y), kB = pack2(k4.z, k4.w);
        ull fA = pack2(f4.x, f4.y), fB = pack2(f4.z, f4.w);
        ull wrA = pack2(w4.x * r4.x, w4.y * r4.y);
        ull wrB = pack2(w4.z * r4.z, w4.w * r4.w);

        float sa[4], d1[4];
#pragma unroll
        for (int i = 0; i < 4; i++) {
            ull sdp = fma2_(S2[i][1], kB, mul2_(S2[i][0], kA));
            float2 su = unpack2(sdp);
            sa[i] = su.x + su.y;
            ull ddp = fma2_(S2[i][1], wrB, mul2_(S2[i][0], wrA));
            float2 du = unpack2(ddp);
            d1[i] = du.x + du.y;
        }

#pragma unroll
        for (int m = 16; m > 0; m >>= 1) {
            sa[0] += __shfl_xor_sync(0xffffffffu, sa[0], m);
            sa[1] += __shfl_xor_sync(0xffffffffu, sa[1], m);
            sa[2] += __shfl_xor_sync(0xffffffffu, sa[2], m);
            sa[3] += __shfl_xor_sync(0xffffffffu, sa[3], m);
            d1[0] += __shfl_xor_sync(0xffffffffu, d1[0], m);
            d1[1] += __shfl_xor_sync(0xffffffffu, d1[1], m);
            d1[2] += __shfl_xor_sync(0xffffffffu, d1[2], m);
            d1[3] += __shfl_xor_sync(0xffffffffu, d1[3], m);
        }
#pragma unroll
        for (int i = 0; i < 4; i++) sa[i] = -sa[i];

        if (lane == 0) {
            float4 yo;
            yo.x = fmaf(sa[0], cc.x, fmaf(v4.x, cc.y, d1[0]));
            yo.y = fmaf(sa[1], cc.x, fmaf(v4.y, cc.y, d1[1]));
            yo.z = fmaf(sa[2], cc.x, fmaf(v4.z, cc.y, d1[2]));
            yo.w = fmaf(sa[3], cc.x, fmaf(v4.w, cc.y, d1[3]));
            *(float4*)&py[(size_t)tt * HN_DIM] = yo;
        }

        const float vv[4] = {v4.x, v4.y, v4.z, v4.w};
#pragma unroll
        for (int i = 0; i < 4; i++) {
            ull sai = pack2(sa[i], sa[i]);
            ull vvi = pack2(vv[i], vv[i]);
            S2[i][0] = fma2_(S2[i][0], wA, fma2_(sai, bA, mul2_(vvi, fA)));
            S2[i][1] = fma2_(S2[i][1], wB, fma2_(sai, bB, mul2_(vvi, fB)));
        }
    };

    // main loop: 341 iterations x 6 steps = 2046 steps
    for (int t = 0; t < T_LEN - 2; t += 6) {
#pragma unroll
        for (int u = 0; u < 6; u++) {
            int tn = t + u + 6;
            if (tn > T_LEN - 1) tn = T_LEN - 1;
            step(u, t + u, true, tn);
        }
    }
    // tail: steps 2046, 2047 live in slots 0, 1
    step(0, T_LEN - 2, false, 0);
    step(1, T_LEN - 1, false, 0);
}

// ---------------- launch ----------------
static float* symAddrF(const void* sym) {
    void* p = nullptr;
    cudaGetSymbolAddress(&p, sym);
    return (float*)p;
}
static float2* symAddrF2(const void* sym) {
    void* p = nullptr;
    cudaGetSymbolAddress(&p, sym);
    return (float2*)p;
}
static __nv_bfloat16* symAddrB(const void* sym) {
    void* p = nullptr;
    cudaGetSymbolAddress(&p, sym);
    return (__nv_bfloat16*)p;
}

extern "C" void kernel_launch(void* const* d_in, const int* in_sizes, int n_in,
                              void* d_out, int out_size) {
    const float* x = (const float*)d_in[0];
    const float* v_first = (const float*)d_in[1];
    const float* k_first = (const float*)d_in[2];
    const float* amask = (const float*)d_in[3];
    const float* cosb = (const float*)d_in[4];
    const float* sinb = (const float*)d_in[5];
    const float* w0 = (const float*)d_in[6];
    const float* w1 = (const float*)d_in[7];
    const float* w2 = (const float*)d_in[8];
    const float* a0 = (const float*)d_in[9];
    const float* a1 = (const float*)d_in[10];
    const float* a2 = (const float*)d_in[11];
    const float* v0 = (const float*)d_in[12];
    const float* v1 = (const float*)d_in[13];
    const float* v2 = (const float*)d_in[14];
    const float* k0 = (const float*)d_in[15];
    const float* k1 = (const float*)d_in[16];
    const float* k2 = (const float*)d_in[17];
    const float* g1 = (const float*)d_in[18];
    const float* g2 = (const float*)d_in[19];
    const float* r_k = (const float*)d_in[20];
    const float* r_norm_w = (const float*)d_in[21];
    const float* k_norm_w = (const float*)d_in[22];
    const float* W_r = (const float*)d_in[23];
    const float* W_k = (const float*)d_in[24];
    const float* W_v = (const float*)d_in[25];
    const float* W_o = (const float*)d_in[26];
    float* out = (float*)d_out;

    float* Ccat = symAddrF(g_Ccat);
    float* wfull = symAddrF(g_wfull);
    float* afull = symAddrF(g_afull);
    float* gfull = symAddrF(g_gfull);
    float* vmix = symAddrF(g_vmix);
    float* kmix = symAddrF(g_kmix);
    float* rrb = symAddrF(g_rr);
    float* kf = symAddrF(g_kf);
    float* vf = symAddrF(g_vf);
    float* kkb = symAddrF(g_kk);
    float* wd = symAddrF(g_wd);
    float* bbb = symAddrF(g_bb);
    float* coef = symAddrF(g_coef);
    float2* c12 = symAddrF2(g_c12);
    float* yb = symAddrF(g_y);
    __nv_bfloat16* Ap = symAddrB(g_Ap);
    __nv_bfloat16* Bp = symAddrB(g_Bp);

    // one-time side stream + events (created on first, non-captured call)
    static cudaStream_t sideStream = nullptr;
    static cudaEvent_t evFork = nullptr, evJoin = nullptr;
    if (sideStream == nullptr) {
        cudaStreamCreateWithFlags(&sideStream, cudaStreamNonBlocking);
        cudaEventCreateWithFlags(&evFork, cudaEventDisableTiming);
        cudaEventCreateWithFlags(&evJoin, cudaEventDisableTiming);
    }

    // ---- stage 1 (main stream) ----
    const int NTC2 = T_LEN * C_DIM / 2;
    splitAmask_kernel<<<(NTC2 + 255) / 256, 256>>>(x, amask, Ap, NTC2);

    const int NB2 = T_LEN * NCAT / 2;
    splitBcat_kernel<<<(NB2 + 255) / 256, 256>>>(W_r, W_k, W_v, w1, a1, v1, k1, g1, Bp, NB2);

    {
        dim3 grid((NCAT + 127) / 128, 2048 / 128);
        bf16_gemm_kernel<<<grid, 256>>>(Ap, Bp, Ccat, 2048, NCAT, 6144, NCAT, NCAT);
    }

    // ---- fused activations + stage-2 A splits ----
    const int NMIDS2 = T_LEN * NMID / 2;
    splitMids_kernel<<<(NMIDS2 + 255) / 256, 256>>>(Ccat, Ap, NMIDS2);

    // ---- stage-2 B splits ----
    {
        const int n2 = 917504 / 2;
        splitB2_kernel<<<(n2 + 255) / 256, 256>>>(w2, a2, g2, v2, k2, Bp, n2);
    }

    // ---- FORK: side stream does g-path GEMM + W_o split (hidden under main work/scan) ----
    cudaEventRecord(evFork, 0);
    cudaStreamWaitEvent(sideStream, evFork, 0);
    {
        dim3 grid(2048 / 128, 2048 / 128);
        bf16_gemm_kernel<<<grid, 256, 0, sideStream>>>(Ap + APG_BASE, Bp + BG_BASE, gfull,
                                                       2048, 2048, 480, 2048, 2048);
        int n2 = 2048 * 2048 / 2;
        splitB_kernel<<<(n2 + 255) / 256, 256, 0, sideStream>>>(W_o, Bp + BWO_BASE, 2048, 2048,
                                                                2048, 0, n2);
    }
    cudaEventRecord(evJoin, sideStream);

    // ---- main stream: remaining stage-2 GEMMs ----
    auto gemm2 = [&](size_t aBase, size_t bBase, int K, float* C, int N) {
        dim3 grid((N + 127) / 128, 2048 / 128);
        bf16_gemm_kernel<<<grid, 256>>>(Ap + aBase, Bp + bBase, C, 2048, N, 3 * K, N, N);
    };
    gemm2(APW_BASE, BW_BASE, 160, wfull, 2048);
    gemm2(APA_BASE, BA_BASE, 96, afull, 2048);
    gemm2(APV_BASE, BV_BASE, 64, vmix, 512);
    gemm2(APK_BASE, BK_BASE, 64, kmix, 512);

    // ---- postprocess (R8 kernels) ----
    pp_kv_kernel<<<dim3(T_LEN, KVH_NUM), 128>>>(Ccat, kmix, vmix, k_first, v_first,
                                                k0, v0, k_norm_w, cosb, sinb,
                                                kf, vf, kkb);
    pp_h_kernel<<<dim3(T_LEN, H_NUM), 128>>>(Ccat, wfull, afull, w0, a0, kkb, kf,
                                             r_norm_w, cosb, sinb, r_k,
                                             rrb, wd, bbb, coef, c12);

    // ---- sequential scan (side-stream work overlaps with this) ----
    scan_kernel<<<dim3(H_NUM, 32), 32>>>(wd, bbb, kkb, kf, rrb, vf, c12, yb);

    // ---- JOIN before consuming gfull / writing Ap ----
    cudaStreamWaitEvent(0, evJoin, 0);

    // ---- fused merge + final A split ----
    const int NHN2 = T_LEN * HN_DIM / 2;
    mergeSplitA_kernel<<<(NHN2 + 255) / 256, 256>>>(yb, coef, vf, gfull, Ap, NHN2);

    // ---- final projection (W_o B' prepared on side stream) ----
    {
        dim3 grid(2048 / 128, 2048 / 128);
        bf16_gemm_kernel<<<grid, 256>>>(Ap, Bp + BWO_BASE, out, 2048, 2048, 6144, 2048, 2048);
    }
}